// round 1
// baseline (speedup 1.0000x reference)
#include <cuda_runtime.h>

#define NN   50000
#define EE   800000
#define FIN  128
#define FH   128
#define FOUT 32
#define KCH  16

// ---------------- device scratch (static: no runtime allocation) ----------------
__device__ float g_T0[NN * FIN];
__device__ float g_T1[NN * FIN];
__device__ float g_T2[NN * FIN];
__device__ float g_H [NN * FH];      // layer-1 accumulator, then h after BN+ReLU
__device__ int   g_degi[NN];
__device__ int   g_cnt [NN];
__device__ int   g_rowptr[NN + 1];
__device__ int   g_cursor[NN];
__device__ float g_dinv[NN];
__device__ int   g_col[EE];
__device__ float g_val[EE];
__device__ float g_bnsum[FH];
__device__ float g_bnsq [FH];
__device__ int   g_is32;             // 1 if edge_index is int32, 0 if int64

// ---------------- build kernels ----------------
__global__ void init_zero(int N) {
    int i = blockIdx.x * blockDim.x + threadIdx.x;
    if (i < N) { g_degi[i] = 0; g_cnt[i] = 0; }
    if (i == 0) g_is32 = 0;
}

__global__ void zero_bn(int C) {
    int i = threadIdx.x;
    if (i < C) { g_bnsum[i] = 0.f; g_bnsq[i] = 0.f; }
}

// If edge_index is int64 (values < 50000, little-endian), every odd 32-bit word
// of the first 2E words is zero. If int32, odd words are random node ids.
__global__ void detect_dtype(const int* __restrict__ p, int E) {
    int i = blockIdx.x * blockDim.x + threadIdx.x;
    if (i < E) {
        if (p[2 * i + 1] != 0) g_is32 = 1;   // benign race: all writers store 1
    }
}

__device__ __forceinline__ void load_edge(const void* ei, int E, int e, int& s, int& d) {
    if (g_is32) {
        const int* p = (const int*)ei;
        s = p[e]; d = p[E + e];
    } else {
        const long long* p = (const long long*)ei;
        s = (int)p[e]; d = (int)p[E + e];
    }
}

__global__ void degree_kernel(const void* __restrict__ ei, int E) {
    int e = blockIdx.x * blockDim.x + threadIdx.x;
    if (e >= E) return;
    int s, d; load_edge(ei, E, e, s, d);
    if (s != d) { atomicAdd(&g_degi[s], 1); atomicAdd(&g_cnt[d], 1); }
}

__global__ void dinv_kernel(int N) {
    int i = blockIdx.x * blockDim.x + threadIdx.x;
    if (i >= N) return;
    int dg = g_degi[i];
    g_dinv[i] = (dg > 0) ? rsqrtf((float)dg) : 0.f;
}

// single-block exclusive scan over g_cnt -> g_rowptr, g_cursor
__global__ void scan_kernel(int N) {
    __shared__ int warpsum[32];
    __shared__ int s_carry;
    __shared__ int s_chunk;
    int t = threadIdx.x, lane = t & 31, wid = t >> 5;
    if (t == 0) s_carry = 0;
    __syncthreads();
    for (int base = 0; base < N; base += 1024) {
        int idx = base + t;
        int v = (idx < N) ? g_cnt[idx] : 0;
        int x = v;
        #pragma unroll
        for (int off = 1; off < 32; off <<= 1) {
            int y = __shfl_up_sync(0xffffffffu, x, off);
            if (lane >= off) x += y;
        }
        if (lane == 31) warpsum[wid] = x;
        __syncthreads();
        if (wid == 0) {
            int w = warpsum[lane];
            int xw = w;
            #pragma unroll
            for (int off = 1; off < 32; off <<= 1) {
                int y = __shfl_up_sync(0xffffffffu, xw, off);
                if (lane >= off) xw += y;
            }
            warpsum[lane] = xw - w;                 // exclusive warp offsets
            if (lane == 31) s_chunk = xw;           // chunk total
        }
        __syncthreads();
        int excl = s_carry + warpsum[wid] + x - v;
        if (idx < N) { g_rowptr[idx] = excl; g_cursor[idx] = excl; }
        __syncthreads();
        if (t == 0) s_carry += s_chunk;
        __syncthreads();
    }
    if (threadIdx.x == 0) g_rowptr[N] = s_carry;
}

__global__ void scatter_kernel(const void* __restrict__ ei, int E) {
    int e = blockIdx.x * blockDim.x + threadIdx.x;
    if (e >= E) return;
    int s, d; load_edge(ei, E, e, s, d);
    if (s != d) {
        int pos = atomicAdd(&g_cursor[d], 1);
        g_col[pos] = s;
        g_val[pos] = -g_dinv[s] * g_dinv[d];
    }
}

// ---------------- SpMM: dst = L @ src  (mode 0)   or   dst = 2*L@src - sub (mode 1)
__global__ void spmm_kernel(const float4* __restrict__ src, const float4* __restrict__ sub,
                            float4* __restrict__ dst, int N, int mode) {
    int warp = (blockIdx.x * blockDim.x + threadIdx.x) >> 5;
    int lane = threadIdx.x & 31;
    if (warp >= N) return;
    int start = g_rowptr[warp], end = g_rowptr[warp + 1];
    float4 acc = make_float4(0.f, 0.f, 0.f, 0.f);
    for (int i = start; i < end; i += 32) {
        int nb = min(32, end - i);
        int c = 0; float v = 0.f;
        if (lane < nb) { c = g_col[i + lane]; v = g_val[i + lane]; }
        for (int j = 0; j < nb; j++) {
            int   cc = __shfl_sync(0xffffffffu, c, j);
            float vv = __shfl_sync(0xffffffffu, v, j);
            float4 xr = src[cc * 32 + lane];
            acc.x = fmaf(vv, xr.x, acc.x);
            acc.y = fmaf(vv, xr.y, acc.y);
            acc.z = fmaf(vv, xr.z, acc.z);
            acc.w = fmaf(vv, xr.w, acc.w);
        }
    }
    if (mode) {
        float4 t = sub[warp * 32 + lane];
        acc.x = 2.f * acc.x - t.x;
        acc.y = 2.f * acc.y - t.y;
        acc.z = 2.f * acc.z - t.z;
        acc.w = 2.f * acc.w - t.w;
    }
    dst[warp * 32 + lane] = acc;
}

// ---------------- GEMM: out[N,BN] (+)= A[N,128] @ W[128,BN]  (+ bias on init) ----
template <int BN, int TM, int TN>
__launch_bounds__(256)
__global__ void gemm_acc(const float* __restrict__ A, const float* __restrict__ W,
                         const float* __restrict__ bias, float* __restrict__ out,
                         int N, int accmode) {
    const int BM = 64, BK = 32;
    __shared__ float sA[BM][BK + 1];
    __shared__ float sB[BK][BN + 1];
    const int NTX = BN / TN;
    int t  = threadIdx.x;
    int tx = t % NTX;
    int ty = t / NTX;
    int rowBase = blockIdx.x * BM;
    float acc[TM][TN];
    #pragma unroll
    for (int i = 0; i < TM; i++)
        #pragma unroll
        for (int j = 0; j < TN; j++) acc[i][j] = 0.f;

    for (int kk = 0; kk < 128; kk += BK) {
        #pragma unroll
        for (int i = t; i < BM * BK; i += 256) {
            int r = i >> 5, c = i & 31;
            int gr = rowBase + r;
            sA[r][c] = (gr < N) ? A[gr * 128 + kk + c] : 0.f;
        }
        #pragma unroll
        for (int i = t; i < BK * BN; i += 256) {
            int r = i / BN, c = i % BN;
            sB[r][c] = W[(kk + r) * BN + c];
        }
        __syncthreads();
        #pragma unroll
        for (int k = 0; k < BK; k++) {
            float a[TM], b[TN];
            #pragma unroll
            for (int i = 0; i < TM; i++) a[i] = sA[ty * TM + i][k];
            #pragma unroll
            for (int j = 0; j < TN; j++) b[j] = sB[k][tx * TN + j];
            #pragma unroll
            for (int i = 0; i < TM; i++)
                #pragma unroll
                for (int j = 0; j < TN; j++)
                    acc[i][j] = fmaf(a[i], b[j], acc[i][j]);
        }
        __syncthreads();
    }
    #pragma unroll
    for (int i = 0; i < TM; i++) {
        int gr = rowBase + ty * TM + i;
        if (gr < N) {
            #pragma unroll
            for (int j = 0; j < TN; j++) {
                int c = tx * TN + j;
                int idx = gr * BN + c;
                float v = acc[i][j];
                out[idx] = accmode ? (out[idx] + v) : (v + bias[c]);
            }
        }
    }
}

// ---------------- BatchNorm ----------------
__global__ void bn_stats(const float* __restrict__ X, int N, int C) {
    int t = threadIdx.x;
    int c = t % C;
    int rr = t / C;
    int rowsPer = blockDim.x / C;
    float s = 0.f, q = 0.f;
    for (int r = blockIdx.x * rowsPer + rr; r < N; r += gridDim.x * rowsPer) {
        float v = X[r * C + c];
        s += v; q = fmaf(v, v, q);
    }
    __shared__ float ss[256], sq[256];
    ss[t] = s; sq[t] = q;
    __syncthreads();
    if (t < C) {
        for (int g = 1; g < rowsPer; g++) { s += ss[t + g * C]; q += sq[t + g * C]; }
        atomicAdd(&g_bnsum[t], s);
        atomicAdd(&g_bnsq [t], q);
    }
}

__global__ void bn_apply_relu(const float* __restrict__ X, float* __restrict__ Y,
                              const float* __restrict__ gamma, const float* __restrict__ beta,
                              int N, int C) {
    int i = blockIdx.x * blockDim.x + threadIdx.x;
    if (i >= N * C) return;
    int c = i % C;
    float invN = 1.f / (float)N;
    float mu  = g_bnsum[c] * invN;
    float var = g_bnsq[c] * invN - mu * mu;
    float y = fmaf(gamma[c] * rsqrtf(var + 1e-5f), X[i] - mu, beta[c]);
    Y[i] = fmaxf(y, 0.f);
}

// ---------------- host ----------------
extern "C" void kernel_launch(void* const* d_in, const int* in_sizes, int n_in,
                              void* d_out, int out_size) {
    const float* x   = (const float*)d_in[0];
    const void*  ei  = d_in[1];
    const float* W1  = (const float*)d_in[2];
    const float* b1  = (const float*)d_in[3];
    const float* W2  = (const float*)d_in[4];
    const float* b2  = (const float*)d_in[5];
    const float* g1  = (const float*)d_in[6];
    const float* be1 = (const float*)d_in[7];
    const float* g2  = (const float*)d_in[8];
    const float* be2 = (const float*)d_in[9];
    float* out = (float*)d_out;

    int N = in_sizes[0] / FIN;
    int E = in_sizes[1] / 2;

    void* pv;
    cudaGetSymbolAddress(&pv, g_T0); float* T0 = (float*)pv;
    cudaGetSymbolAddress(&pv, g_T1); float* T1 = (float*)pv;
    cudaGetSymbolAddress(&pv, g_T2); float* T2 = (float*)pv;
    cudaGetSymbolAddress(&pv, g_H);  float* H  = (float*)pv;

    int gE = (E + 255) / 256;
    int gN = (N + 255) / 256;
    int gGemm = (N + 63) / 64;
    int gSp = (N * 32 + 255) / 256;

    // ---- graph build ----
    init_zero<<<gN, 256>>>(N);
    detect_dtype<<<gE, 256>>>((const int*)ei, E);
    degree_kernel<<<gE, 256>>>(ei, E);
    dinv_kernel<<<gN, 256>>>(N);
    scan_kernel<<<1, 1024>>>(N);
    scatter_kernel<<<gE, 256>>>(ei, E);

    float* bufs[3] = {T0, T1, T2};

    // ---- layer 1 ----
    gemm_acc<128, 4, 8><<<gGemm, 256>>>(x, W1, b1, H, N, 0);
    spmm_kernel<<<gSp, 256>>>((const float4*)x, nullptr, (float4*)T1, N, 0);
    gemm_acc<128, 4, 8><<<gGemm, 256>>>(T1, W1 + FIN * FH, b1, H, N, 1);
    {
        const float* pp = x;
        const float* pc = T1;
        for (int k = 2; k < KCH; k++) {
            float* nxt = bufs[k % 3];
            spmm_kernel<<<gSp, 256>>>((const float4*)pc, (const float4*)pp, (float4*)nxt, N, 1);
            gemm_acc<128, 4, 8><<<gGemm, 256>>>(nxt, W1 + k * FIN * FH, b1, H, N, 1);
            pp = pc; pc = nxt;
        }
    }
    zero_bn<<<1, 128>>>(FH);
    bn_stats<<<512, 256>>>(H, N, FH);
    bn_apply_relu<<<(N * FH + 255) / 256, 256>>>(H, H, g1, be1, N, FH);

    // ---- layer 2 ----
    gemm_acc<32, 4, 2><<<gGemm, 256>>>(H, W2, b2, out, N, 0);
    spmm_kernel<<<gSp, 256>>>((const float4*)H, nullptr, (float4*)T1, N, 0);
    gemm_acc<32, 4, 2><<<gGemm, 256>>>(T1, W2 + FH * FOUT, b2, out, N, 1);
    {
        const float* pp = H;
        const float* pc = T1;
        for (int k = 2; k < KCH; k++) {
            float* nxt = bufs[k % 3];
            spmm_kernel<<<gSp, 256>>>((const float4*)pc, (const float4*)pp, (float4*)nxt, N, 1);
            gemm_acc<32, 4, 2><<<gGemm, 256>>>(nxt, W2 + k * FH * FOUT, b2, out, N, 1);
            pp = pc; pc = nxt;
        }
    }
    zero_bn<<<1, 128>>>(FOUT);
    bn_stats<<<512, 256>>>(out, N, FOUT);
    bn_apply_relu<<<(N * FOUT + 255) / 256, 256>>>(out, out, g2, be2, N, FOUT);
}

// round 2
// speedup vs baseline: 2.1536x; 2.1536x over previous
#include <cuda_runtime.h>

#define NN   50000
#define EE   800000
#define FIN  128
#define FH   128
#define FOUT 32
#define KCH  16

// ---------------- device scratch (static: no runtime allocation) ----------------
__device__ float g_S1[NN * (KCH * FH)];    // 50000 x 2048  (layer-1 projections)
__device__ float g_S2[NN * (KCH * FOUT)];  // 50000 x 512   (layer-2 projections)
__device__ float g_W1c[FIN * KCH * FH];    // 128 x 2048
__device__ float g_W2c[FH * KCH * FOUT];   // 128 x 512
__device__ float g_T0[NN * FH];
__device__ float g_T1[NN * FH];
__device__ float g_T2[NN * FH];
__device__ float g_H [NN * FH];
__device__ int   g_degi[NN];
__device__ int   g_cnt [NN];
__device__ int   g_rowptr[NN + 1];
__device__ int   g_cursor[NN];
__device__ float g_dinv[NN];
__device__ int   g_col[EE];
__device__ float g_val[EE];
__device__ float g_bnsum[FH];
__device__ float g_bnsq [FH];
__device__ int   g_is32;

// ---------------- helpers ----------------
__device__ __forceinline__ unsigned f2tf32(float f) {
    unsigned r;
    asm("cvt.rna.tf32.f32 %0, %1;" : "=r"(r) : "f"(f));
    return r;
}

__device__ __forceinline__ void mma_tf32(float* c, const unsigned* a, const unsigned* b) {
    asm volatile("mma.sync.aligned.m16n8k8.row.col.f32.tf32.tf32.f32 "
        "{%0,%1,%2,%3}, {%4,%5,%6,%7}, {%8,%9}, {%0,%1,%2,%3};"
        : "+f"(c[0]), "+f"(c[1]), "+f"(c[2]), "+f"(c[3])
        : "r"(a[0]), "r"(a[1]), "r"(a[2]), "r"(a[3]), "r"(b[0]), "r"(b[1]));
}

// ---------------- build kernels ----------------
__global__ void init_zero(int N) {
    int i = blockIdx.x * blockDim.x + threadIdx.x;
    if (i < N) { g_degi[i] = 0; g_cnt[i] = 0; }
    if (i == 0) g_is32 = 0;
}

__global__ void zero_bn(int C) {
    int i = threadIdx.x;
    if (i < C) { g_bnsum[i] = 0.f; g_bnsq[i] = 0.f; }
}

__global__ void detect_dtype(const int* __restrict__ p, int E) {
    int i = blockIdx.x * blockDim.x + threadIdx.x;
    if (i < E) {
        if (p[2 * i + 1] != 0) g_is32 = 1;
    }
}

__device__ __forceinline__ void load_edge(const void* ei, int E, int e, int& s, int& d) {
    if (g_is32) {
        const int* p = (const int*)ei;
        s = p[e]; d = p[E + e];
    } else {
        const long long* p = (const long long*)ei;
        s = (int)p[e]; d = (int)p[E + e];
    }
}

__global__ void degree_kernel(const void* __restrict__ ei, int E) {
    int e = blockIdx.x * blockDim.x + threadIdx.x;
    if (e >= E) return;
    int s, d; load_edge(ei, E, e, s, d);
    if (s != d) { atomicAdd(&g_degi[s], 1); atomicAdd(&g_cnt[d], 1); }
}

__global__ void dinv_kernel(int N) {
    int i = blockIdx.x * blockDim.x + threadIdx.x;
    if (i >= N) return;
    int dg = g_degi[i];
    g_dinv[i] = (dg > 0) ? rsqrtf((float)dg) : 0.f;
}

__global__ void scan_kernel(int N) {
    __shared__ int warpsum[32];
    __shared__ int s_carry;
    __shared__ int s_chunk;
    int t = threadIdx.x, lane = t & 31, wid = t >> 5;
    if (t == 0) s_carry = 0;
    __syncthreads();
    for (int base = 0; base < N; base += 1024) {
        int idx = base + t;
        int v = (idx < N) ? g_cnt[idx] : 0;
        int x = v;
        #pragma unroll
        for (int off = 1; off < 32; off <<= 1) {
            int y = __shfl_up_sync(0xffffffffu, x, off);
            if (lane >= off) x += y;
        }
        if (lane == 31) warpsum[wid] = x;
        __syncthreads();
        if (wid == 0) {
            int w = warpsum[lane];
            int xw = w;
            #pragma unroll
            for (int off = 1; off < 32; off <<= 1) {
                int y = __shfl_up_sync(0xffffffffu, xw, off);
                if (lane >= off) xw += y;
            }
            warpsum[lane] = xw - w;
            if (lane == 31) s_chunk = xw;
        }
        __syncthreads();
        int excl = s_carry + warpsum[wid] + x - v;
        if (idx < N) { g_rowptr[idx] = excl; g_cursor[idx] = excl; }
        __syncthreads();
        if (t == 0) s_carry += s_chunk;
        __syncthreads();
    }
    if (threadIdx.x == 0) g_rowptr[N] = s_carry;
}

__global__ void scatter_kernel(const void* __restrict__ ei, int E) {
    int e = blockIdx.x * blockDim.x + threadIdx.x;
    if (e >= E) return;
    int s, d; load_edge(ei, E, e, s, d);
    if (s != d) {
        int pos = atomicAdd(&g_cursor[d], 1);
        g_col[pos] = s;
        g_val[pos] = -g_dinv[s] * g_dinv[d];
    }
}

// ---------------- weight concat: W[k][f][o] -> Wc[f][k*O + o] ----------------
__global__ void concat_w1(const float* __restrict__ W, float* __restrict__ Wc) {
    int idx = blockIdx.x * blockDim.x + threadIdx.x;
    if (idx >= KCH * FIN * FH) return;
    int k = idx >> 14;           // / (128*128)
    int f = (idx >> 7) & 127;
    int o = idx & 127;
    Wc[f * (KCH * FH) + k * FH + o] = W[idx];
}

__global__ void concat_w2(const float* __restrict__ W, float* __restrict__ Wc) {
    int idx = blockIdx.x * blockDim.x + threadIdx.x;
    if (idx >= KCH * FH * FOUT) return;
    int k = idx >> 12;           // / (128*32)
    int f = (idx >> 5) & 127;
    int o = idx & 31;
    Wc[f * (KCH * FOUT) + k * FOUT + o] = W[idx];
}

// ---------------- TF32 GEMM: C[N, NC] = A[N,128] @ B[128, NC] ----------------
// BM=128, BN=128, BK=32. 256 threads = 8 warps in 2x4 layout (64x32 warp tile).
__global__ __launch_bounds__(256) void gemm_tf32(const float* __restrict__ A,
                                                 const float* __restrict__ B,
                                                 float* __restrict__ C,
                                                 int N, int NC) {
    __shared__ unsigned sA[128][36];
    __shared__ unsigned sB[32][132];
    int t = threadIdx.x;
    int lane = t & 31;
    int warp = t >> 5;
    int wm0 = (warp & 1) * 64;
    int wn0 = (warp >> 1) * 32;
    int bm0 = blockIdx.x * 128;
    int bn0 = blockIdx.y * 128;

    float c[4][4][4];
    #pragma unroll
    for (int mi = 0; mi < 4; mi++)
        #pragma unroll
        for (int ni = 0; ni < 4; ni++)
            #pragma unroll
            for (int r = 0; r < 4; r++) c[mi][ni][r] = 0.f;

    for (int kt = 0; kt < 128; kt += 32) {
        // load A tile 128x32 (as 128x8 float4)
        #pragma unroll
        for (int i = 0; i < 4; i++) {
            int id = t + i * 256;
            int r = id >> 3, c4 = id & 7;
            float4 v = make_float4(0.f, 0.f, 0.f, 0.f);
            int gr = bm0 + r;
            if (gr < N) v = *(const float4*)&A[gr * 128 + kt + c4 * 4];
            sA[r][c4 * 4 + 0] = f2tf32(v.x);
            sA[r][c4 * 4 + 1] = f2tf32(v.y);
            sA[r][c4 * 4 + 2] = f2tf32(v.z);
            sA[r][c4 * 4 + 3] = f2tf32(v.w);
        }
        // load B tile 32x128 (as 32x32 float4)
        #pragma unroll
        for (int i = 0; i < 4; i++) {
            int id = t + i * 256;
            int r = id >> 5, c4 = id & 31;
            float4 v = *(const float4*)&B[(kt + r) * NC + bn0 + c4 * 4];
            sB[r][c4 * 4 + 0] = f2tf32(v.x);
            sB[r][c4 * 4 + 1] = f2tf32(v.y);
            sB[r][c4 * 4 + 2] = f2tf32(v.z);
            sB[r][c4 * 4 + 3] = f2tf32(v.w);
        }
        __syncthreads();
        #pragma unroll
        for (int k8 = 0; k8 < 32; k8 += 8) {
            unsigned a[4][4], b[4][2];
            #pragma unroll
            for (int mi = 0; mi < 4; mi++) {
                int row = wm0 + mi * 16 + (lane >> 2);
                int col = k8 + (lane & 3);
                a[mi][0] = sA[row][col];
                a[mi][1] = sA[row + 8][col];
                a[mi][2] = sA[row][col + 4];
                a[mi][3] = sA[row + 8][col + 4];
            }
            #pragma unroll
            for (int ni = 0; ni < 4; ni++) {
                int kk = k8 + (lane & 3);
                int nn = wn0 + ni * 8 + (lane >> 2);
                b[ni][0] = sB[kk][nn];
                b[ni][1] = sB[kk + 4][nn];
            }
            #pragma unroll
            for (int mi = 0; mi < 4; mi++)
                #pragma unroll
                for (int ni = 0; ni < 4; ni++)
                    mma_tf32(c[mi][ni], a[mi], b[ni]);
        }
        __syncthreads();
    }

    #pragma unroll
    for (int mi = 0; mi < 4; mi++) {
        #pragma unroll
        for (int ni = 0; ni < 4; ni++) {
            int gr = bm0 + wm0 + mi * 16 + (lane >> 2);
            int gc = bn0 + wn0 + ni * 8 + 2 * (lane & 3);
            if (gr < N) {
                C[gr * NC + gc]     = c[mi][ni][0];
                C[gr * NC + gc + 1] = c[mi][ni][1];
            }
            if (gr + 8 < N) {
                C[(gr + 8) * NC + gc]     = c[mi][ni][2];
                C[(gr + 8) * NC + gc + 1] = c[mi][ni][3];
            }
        }
    }
}

// ---------------- Clenshaw SpMM, 128 features: dst = S + two*(L@b1) - b2 (+bias) --
__global__ void cheb_spmm128(const float4* __restrict__ b1, int ldb1,
                             const float4* __restrict__ b2, int ldb2,
                             const float4* __restrict__ S, int ldS,
                             float4* __restrict__ dst,
                             const float4* __restrict__ bias,
                             float two, int N) {
    int row = (blockIdx.x * blockDim.x + threadIdx.x) >> 5;
    int lane = threadIdx.x & 31;
    if (row >= N) return;
    int start = g_rowptr[row], end = g_rowptr[row + 1];
    float4 acc = make_float4(0.f, 0.f, 0.f, 0.f);
    for (int i = start; i < end; i += 32) {
        int nb = min(32, end - i);
        int c = 0; float v = 0.f;
        if (lane < nb) { c = g_col[i + lane]; v = g_val[i + lane]; }
        for (int j = 0; j < nb; j++) {
            int   cc = __shfl_sync(0xffffffffu, c, j);
            float vv = __shfl_sync(0xffffffffu, v, j);
            float4 xr = b1[cc * ldb1 + lane];
            acc.x = fmaf(vv, xr.x, acc.x);
            acc.y = fmaf(vv, xr.y, acc.y);
            acc.z = fmaf(vv, xr.z, acc.z);
            acc.w = fmaf(vv, xr.w, acc.w);
        }
    }
    float4 s = S[row * ldS + lane];
    float4 r;
    r.x = fmaf(two, acc.x, s.x);
    r.y = fmaf(two, acc.y, s.y);
    r.z = fmaf(two, acc.z, s.z);
    r.w = fmaf(two, acc.w, s.w);
    if (b2) {
        float4 t = b2[row * ldb2 + lane];
        r.x -= t.x; r.y -= t.y; r.z -= t.z; r.w -= t.w;
    }
    if (bias) {
        float4 bb = bias[lane];
        r.x += bb.x; r.y += bb.y; r.z += bb.z; r.w += bb.w;
    }
    dst[row * 32 + lane] = r;
}

// ---------------- Clenshaw SpMM, 32 features ----------------
__global__ void cheb_spmm32(const float* __restrict__ b1, int ldb1,
                            const float* __restrict__ b2, int ldb2,
                            const float* __restrict__ S, int ldS,
                            float* __restrict__ dst,
                            const float* __restrict__ bias,
                            float two, int N) {
    int row = (blockIdx.x * blockDim.x + threadIdx.x) >> 5;
    int lane = threadIdx.x & 31;
    if (row >= N) return;
    int start = g_rowptr[row], end = g_rowptr[row + 1];
    float acc = 0.f;
    for (int i = start; i < end; i += 32) {
        int nb = min(32, end - i);
        int c = 0; float v = 0.f;
        if (lane < nb) { c = g_col[i + lane]; v = g_val[i + lane]; }
        for (int j = 0; j < nb; j++) {
            int   cc = __shfl_sync(0xffffffffu, c, j);
            float vv = __shfl_sync(0xffffffffu, v, j);
            acc = fmaf(vv, b1[cc * ldb1 + lane], acc);
        }
    }
    float r = fmaf(two, acc, S[row * ldS + lane]);
    if (b2)  r -= b2[row * ldb2 + lane];
    if (bias) r += bias[lane];
    dst[row * 32 + lane] = r;
}

// ---------------- BatchNorm ----------------
__global__ void bn_stats(const float* __restrict__ X, int N, int C) {
    int t = threadIdx.x;
    int c = t % C;
    int rr = t / C;
    int rowsPer = blockDim.x / C;
    float s = 0.f, q = 0.f;
    for (int r = blockIdx.x * rowsPer + rr; r < N; r += gridDim.x * rowsPer) {
        float v = X[r * C + c];
        s += v; q = fmaf(v, v, q);
    }
    __shared__ float ss[256], sq[256];
    ss[t] = s; sq[t] = q;
    __syncthreads();
    if (t < C) {
        for (int g = 1; g < rowsPer; g++) { s += ss[t + g * C]; q += sq[t + g * C]; }
        atomicAdd(&g_bnsum[t], s);
        atomicAdd(&g_bnsq [t], q);
    }
}

__global__ void bn_apply_relu(const float* __restrict__ X, float* __restrict__ Y,
                              const float* __restrict__ gamma, const float* __restrict__ beta,
                              int N, int C) {
    int i = blockIdx.x * blockDim.x + threadIdx.x;
    if (i >= N * C) return;
    int c = i % C;
    float invN = 1.f / (float)N;
    float mu  = g_bnsum[c] * invN;
    float var = g_bnsq[c] * invN - mu * mu;
    float y = fmaf(gamma[c] * rsqrtf(var + 1e-5f), X[i] - mu, beta[c]);
    Y[i] = fmaxf(y, 0.f);
}

// ---------------- host ----------------
extern "C" void kernel_launch(void* const* d_in, const int* in_sizes, int n_in,
                              void* d_out, int out_size) {
    const float* x    = (const float*)d_in[0];
    const void*  ei   = d_in[1];
    const float* W1   = (const float*)d_in[2];
    const float* b1v  = (const float*)d_in[3];
    const float* W2   = (const float*)d_in[4];
    const float* b2v  = (const float*)d_in[5];
    const float* g1   = (const float*)d_in[6];
    const float* be1  = (const float*)d_in[7];
    const float* g2   = (const float*)d_in[8];
    const float* be2  = (const float*)d_in[9];
    float* out = (float*)d_out;

    int N = in_sizes[0] / FIN;
    int E = in_sizes[1] / 2;

    void* pv;
    cudaGetSymbolAddress(&pv, g_S1);  float* S1  = (float*)pv;
    cudaGetSymbolAddress(&pv, g_S2);  float* S2  = (float*)pv;
    cudaGetSymbolAddress(&pv, g_W1c); float* W1c = (float*)pv;
    cudaGetSymbolAddress(&pv, g_W2c); float* W2c = (float*)pv;
    cudaGetSymbolAddress(&pv, g_T0);  float* T0  = (float*)pv;
    cudaGetSymbolAddress(&pv, g_T1);  float* T1  = (float*)pv;
    cudaGetSymbolAddress(&pv, g_T2);  float* T2  = (float*)pv;
    cudaGetSymbolAddress(&pv, g_H);   float* H   = (float*)pv;

    int gE = (E + 255) / 256;
    int gN = (N + 255) / 256;
    int gSp = (N * 32 + 255) / 256;
    int gM = (N + 127) / 128;

    // ---- graph build ----
    init_zero<<<gN, 256>>>(N);
    detect_dtype<<<gE, 256>>>((const int*)ei, E);
    degree_kernel<<<gE, 256>>>(ei, E);
    dinv_kernel<<<gN, 256>>>(N);
    scan_kernel<<<1, 1024>>>(N);
    scatter_kernel<<<gE, 256>>>(ei, E);

    // ---- weight concat ----
    concat_w1<<<(KCH * FIN * FH + 255) / 256, 256>>>(W1, W1c);
    concat_w2<<<(KCH * FH * FOUT + 255) / 256, 256>>>(W2, W2c);

    float* bufs[3] = {T0, T1, T2};

    // ======== Layer 1 ========
    // S1[N, 2048] = x @ W1c
    gemm_tf32<<<dim3(gM, KCH * FH / 128), 256>>>(x, W1c, S1, N, KCH * FH);

    // Clenshaw: b_15 = S_15 (pointer), b_k = S_k + 2 L b_{k+1} - b_{k+2}
    {
        const float4* b1p = (const float4*)(S1 + 15 * FH); int ldb1 = (KCH * FH) / 4;
        const float4* b2p = nullptr; int ldb2 = 0;
        int bi = 0;
        for (int k = 14; k >= 1; k--) {
            float4* d = (float4*)bufs[bi];
            cheb_spmm128<<<gSp, 256>>>(b1p, ldb1, b2p, ldb2,
                                       (const float4*)(S1 + k * FH), (KCH * FH) / 4,
                                       d, nullptr, 2.f, N);
            b2p = b1p; ldb2 = ldb1;
            b1p = (const float4*)d; ldb1 = 32;
            bi = (bi + 1) % 3;
        }
        // H = S_0 + L b_1 - b_2 + bias1
        cheb_spmm128<<<gSp, 256>>>(b1p, ldb1, b2p, ldb2,
                                   (const float4*)S1, (KCH * FH) / 4,
                                   (float4*)H, (const float4*)b1v, 1.f, N);
    }
    zero_bn<<<1, 128>>>(FH);
    bn_stats<<<512, 256>>>(H, N, FH);
    bn_apply_relu<<<(N * FH + 255) / 256, 256>>>(H, H, g1, be1, N, FH);

    // ======== Layer 2 ========
    // S2[N, 512] = H @ W2c
    gemm_tf32<<<dim3(gM, KCH * FOUT / 128), 256>>>(H, W2c, S2, N, KCH * FOUT);

    {
        const float* b1p = S2 + 15 * FOUT; int ldb1 = KCH * FOUT;
        const float* b2p = nullptr; int ldb2 = 0;
        int bi = 0;
        for (int k = 14; k >= 1; k--) {
            float* d = bufs[bi];
            cheb_spmm32<<<gSp, 256>>>(b1p, ldb1, b2p, ldb2,
                                      S2 + k * FOUT, KCH * FOUT,
                                      d, nullptr, 2.f, N);
            b2p = b1p; ldb2 = ldb1;
            b1p = d; ldb1 = FOUT;
            bi = (bi + 1) % 3;
        }
        cheb_spmm32<<<gSp, 256>>>(b1p, ldb1, b2p, ldb2,
                                  S2, KCH * FOUT,
                                  out, b2v, 1.f, N);
    }
    zero_bn<<<1, 128>>>(FOUT);
    bn_stats<<<512, 256>>>(out, N, FOUT);
    bn_apply_relu<<<(N * FOUT + 255) / 256, 256>>>(out, out, g2, be2, N, FOUT);
}

// round 3
// speedup vs baseline: 2.3512x; 1.0918x over previous
#include <cuda_runtime.h>
#include <cstdint>

#define NN   50000
#define EE   800000
#define FIN  128
#define FH   128
#define FOUT 32
#define KCH  16

// ---------------- device scratch ----------------
__device__ float g_S1[NN * (KCH * FH)];    // 50000 x 2048
__device__ float g_S2[NN * (KCH * FOUT)];  // 50000 x 512
__device__ float g_W1c[FIN * KCH * FH];
__device__ float g_W2c[FH * KCH * FOUT];
__device__ float g_T0[NN * FH];
__device__ float g_T1[NN * FH];
__device__ float g_T2[NN * FH];
__device__ float g_H [NN * FH];
__device__ int   g_degi[NN];
__device__ int   g_cnt [NN];
__device__ int   g_rowptr[NN + 1];
__device__ int   g_cursor[NN];
__device__ float g_dinv[NN];
__device__ int2  g_colval[EE];             // packed (col, val-bits)
__device__ float g_bnsum[FH];
__device__ float g_bnsq [FH];
__device__ int   g_is32;

// ---------------- helpers ----------------
__device__ __forceinline__ unsigned f2tf32(float f) {
    unsigned r;
    asm("cvt.rna.tf32.f32 %0, %1;" : "=r"(r) : "f"(f));
    return r;
}

__device__ __forceinline__ void mma_tf32(float* c, const unsigned* a, const unsigned* b) {
    asm volatile("mma.sync.aligned.m16n8k8.row.col.f32.tf32.tf32.f32 "
        "{%0,%1,%2,%3}, {%4,%5,%6,%7}, {%8,%9}, {%0,%1,%2,%3};"
        : "+f"(c[0]), "+f"(c[1]), "+f"(c[2]), "+f"(c[3])
        : "r"(a[0]), "r"(a[1]), "r"(a[2]), "r"(a[3]), "r"(b[0]), "r"(b[1]));
}

__device__ __forceinline__ void cp_async16(uint32_t dst, const void* src, int szbytes) {
    asm volatile("cp.async.cg.shared.global [%0], [%1], 16, %2;"
                 :: "r"(dst), "l"(src), "r"(szbytes));
}
__device__ __forceinline__ void cp_commit() {
    asm volatile("cp.async.commit_group;");
}
template <int NW>
__device__ __forceinline__ void cp_wait() {
    asm volatile("cp.async.wait_group %0;" :: "n"(NW));
}

// ---------------- build kernels ----------------
__global__ void init_zero(int N) {
    int i = blockIdx.x * blockDim.x + threadIdx.x;
    if (i < N) { g_degi[i] = 0; g_cnt[i] = 0; }
    if (i == 0) g_is32 = 0;
}

__global__ void zero_bn(int C) {
    int i = threadIdx.x;
    if (i < C) { g_bnsum[i] = 0.f; g_bnsq[i] = 0.f; }
}

__global__ void detect_dtype(const int* __restrict__ p, int E) {
    int i = blockIdx.x * blockDim.x + threadIdx.x;
    if (i < E) {
        if (p[2 * i + 1] != 0) g_is32 = 1;
    }
}

__device__ __forceinline__ void load_edge(const void* ei, int E, int e, int& s, int& d) {
    if (g_is32) {
        const int* p = (const int*)ei;
        s = p[e]; d = p[E + e];
    } else {
        const long long* p = (const long long*)ei;
        s = (int)p[e]; d = (int)p[E + e];
    }
}

__global__ void degree_kernel(const void* __restrict__ ei, int E) {
    int e = blockIdx.x * blockDim.x + threadIdx.x;
    if (e >= E) return;
    int s, d; load_edge(ei, E, e, s, d);
    if (s != d) { atomicAdd(&g_degi[s], 1); atomicAdd(&g_cnt[d], 1); }
}

__global__ void dinv_kernel(int N) {
    int i = blockIdx.x * blockDim.x + threadIdx.x;
    if (i >= N) return;
    int dg = g_degi[i];
    g_dinv[i] = (dg > 0) ? rsqrtf((float)dg) : 0.f;
}

__global__ void scan_kernel(int N) {
    __shared__ int warpsum[32];
    __shared__ int s_carry;
    __shared__ int s_chunk;
    int t = threadIdx.x, lane = t & 31, wid = t >> 5;
    if (t == 0) s_carry = 0;
    __syncthreads();
    for (int base = 0; base < N; base += 1024) {
        int idx = base + t;
        int v = (idx < N) ? g_cnt[idx] : 0;
        int x = v;
        #pragma unroll
        for (int off = 1; off < 32; off <<= 1) {
            int y = __shfl_up_sync(0xffffffffu, x, off);
            if (lane >= off) x += y;
        }
        if (lane == 31) warpsum[wid] = x;
        __syncthreads();
        if (wid == 0) {
            int w = warpsum[lane];
            int xw = w;
            #pragma unroll
            for (int off = 1; off < 32; off <<= 1) {
                int y = __shfl_up_sync(0xffffffffu, xw, off);
                if (lane >= off) xw += y;
            }
            warpsum[lane] = xw - w;
            if (lane == 31) s_chunk = xw;
        }
        __syncthreads();
        int excl = s_carry + warpsum[wid] + x - v;
        if (idx < N) { g_rowptr[idx] = excl; g_cursor[idx] = excl; }
        __syncthreads();
        if (t == 0) s_carry += s_chunk;
        __syncthreads();
    }
    if (threadIdx.x == 0) g_rowptr[N] = s_carry;
}

__global__ void scatter_kernel(const void* __restrict__ ei, int E) {
    int e = blockIdx.x * blockDim.x + threadIdx.x;
    if (e >= E) return;
    int s, d; load_edge(ei, E, e, s, d);
    if (s != d) {
        int pos = atomicAdd(&g_cursor[d], 1);
        float v = -g_dinv[s] * g_dinv[d];
        g_colval[pos] = make_int2(s, __float_as_int(v));
    }
}

// ---------------- weight concat ----------------
__global__ void concat_w1(const float* __restrict__ W, float* __restrict__ Wc) {
    int idx = blockIdx.x * blockDim.x + threadIdx.x;
    if (idx >= KCH * FIN * FH) return;
    int k = idx >> 14;
    int f = (idx >> 7) & 127;
    int o = idx & 127;
    Wc[f * (KCH * FH) + k * FH + o] = W[idx];
}

__global__ void concat_w2(const float* __restrict__ W, float* __restrict__ Wc) {
    int idx = blockIdx.x * blockDim.x + threadIdx.x;
    if (idx >= KCH * FH * FOUT) return;
    int k = idx >> 12;
    int f = (idx >> 5) & 127;
    int o = idx & 31;
    Wc[f * (KCH * FOUT) + k * FOUT + o] = W[idx];
}

// ---------------- TF32 GEMM v2: C[N,NC] = A[N,128] @ B[128,NC] ----------------
// BM=128, BN=256, BK=32, 256 threads = 8 warps (2x4), warp tile 64x64.
// Double-buffered cp.async. Dynamic smem:
//   sA[2][128][36]  (stride 36: banks 4r+c, conflict-free)
//   sB[2][32][264]  (stride 264 = 8 mod 32: conflict-free)
#define SA_STRIDE 36
#define SB_STRIDE 264
#define SA_STAGE  (128 * SA_STRIDE)
#define SB_STAGE  (32 * SB_STRIDE)
#define GEMM_SMEM ((2 * SA_STAGE + 2 * SB_STAGE) * 4)

__global__ __launch_bounds__(256, 1) void gemm_tf32(const float* __restrict__ A,
                                                    const float* __restrict__ B,
                                                    float* __restrict__ C,
                                                    int N, int NC) {
    extern __shared__ float smem[];
    float* sA = smem;
    float* sB = smem + 2 * SA_STAGE;
    uint32_t sA_u = (uint32_t)__cvta_generic_to_shared(sA);
    uint32_t sB_u = (uint32_t)__cvta_generic_to_shared(sB);

    int t = threadIdx.x;
    int lane = t & 31;
    int warp = t >> 5;
    int wm0 = (warp & 1) * 64;
    int wn0 = (warp >> 1) * 64;
    int bm0 = blockIdx.x * 128;
    int bn0 = blockIdx.y * 256;

    float c[4][8][4];
    #pragma unroll
    for (int mi = 0; mi < 4; mi++)
        #pragma unroll
        for (int ni = 0; ni < 8; ni++)
            #pragma unroll
            for (int r = 0; r < 4; r++) c[mi][ni][r] = 0.f;

    auto prefetch = [&](int stage, int kt) {
        // A: 128x32 floats = 1024 16B-chunks
        #pragma unroll
        for (int i = 0; i < 4; i++) {
            int id = t + i * 256;
            int row = id >> 3, c4 = id & 7;
            int gr = bm0 + row;
            int ok = (gr < N);
            int grs = ok ? gr : 0;
            uint32_t dst = sA_u + (stage * SA_STAGE + row * SA_STRIDE + c4 * 4) * 4;
            cp_async16(dst, &A[(size_t)grs * 128 + kt + c4 * 4], ok ? 16 : 0);
        }
        // B: 32x256 floats = 2048 16B-chunks
        #pragma unroll
        for (int i = 0; i < 8; i++) {
            int id = t + i * 256;
            int row = id >> 6, c4 = id & 63;
            uint32_t dst = sB_u + (stage * SB_STAGE + row * SB_STRIDE + c4 * 4) * 4;
            cp_async16(dst, &B[(size_t)(kt + row) * NC + bn0 + c4 * 4], 16);
        }
        cp_commit();
    };

    prefetch(0, 0);

    #pragma unroll
    for (int it = 0; it < 4; it++) {
        if (it < 3) prefetch((it + 1) & 1, (it + 1) * 32);
        if (it < 3) cp_wait<1>(); else cp_wait<0>();
        __syncthreads();

        const float* cA = sA + (it & 1) * SA_STAGE;
        const float* cB = sB + (it & 1) * SB_STAGE;
        #pragma unroll
        for (int k8 = 0; k8 < 32; k8 += 8) {
            unsigned a[4][4], b[8][2];
            #pragma unroll
            for (int mi = 0; mi < 4; mi++) {
                int row = wm0 + mi * 16 + (lane >> 2);
                int col = k8 + (lane & 3);
                a[mi][0] = f2tf32(cA[row * SA_STRIDE + col]);
                a[mi][1] = f2tf32(cA[(row + 8) * SA_STRIDE + col]);
                a[mi][2] = f2tf32(cA[row * SA_STRIDE + col + 4]);
                a[mi][3] = f2tf32(cA[(row + 8) * SA_STRIDE + col + 4]);
            }
            #pragma unroll
            for (int ni = 0; ni < 8; ni++) {
                int kk = k8 + (lane & 3);
                int nn = wn0 + ni * 8 + (lane >> 2);
                b[ni][0] = f2tf32(cB[kk * SB_STRIDE + nn]);
                b[ni][1] = f2tf32(cB[(kk + 4) * SB_STRIDE + nn]);
            }
            #pragma unroll
            for (int mi = 0; mi < 4; mi++)
                #pragma unroll
                for (int ni = 0; ni < 8; ni++)
                    mma_tf32(c[mi][ni], a[mi], b[ni]);
        }
        __syncthreads();
    }

    #pragma unroll
    for (int mi = 0; mi < 4; mi++) {
        #pragma unroll
        for (int ni = 0; ni < 8; ni++) {
            int gr = bm0 + wm0 + mi * 16 + (lane >> 2);
            int gc = bn0 + wn0 + ni * 8 + 2 * (lane & 3);
            if (gr < N)
                *(float2*)&C[(size_t)gr * NC + gc] = make_float2(c[mi][ni][0], c[mi][ni][1]);
            if (gr + 8 < N)
                *(float2*)&C[(size_t)(gr + 8) * NC + gc] = make_float2(c[mi][ni][2], c[mi][ni][3]);
        }
    }
}

// ---------------- Clenshaw SpMM, 128 features ----------------
// dst = S + two*(L@b1) - b2 (+bias); optionally accumulate BN stats.
__global__ void cheb_spmm128(const float4* __restrict__ b1, int ldb1,
                             const float4* __restrict__ b2, int ldb2,
                             const float4* __restrict__ S, int ldS,
                             float4* __restrict__ dst,
                             const float4* __restrict__ bias,
                             float two, int N, int stats) {
    __shared__ float ssum[128], ssq[128];
    int row = (blockIdx.x * blockDim.x + threadIdx.x) >> 5;
    int lane = threadIdx.x & 31;
    if (stats) {
        if (threadIdx.x < 128) { ssum[threadIdx.x] = 0.f; ssq[threadIdx.x] = 0.f; }
        __syncthreads();
    }
    if (row < N) {
        int start = g_rowptr[row], end = g_rowptr[row + 1];
        float4 acc = make_float4(0.f, 0.f, 0.f, 0.f);
        for (int i = start; i < end; i += 32) {
            int nb = min(32, end - i);
            int c = 0; float v = 0.f;
            if (lane < nb) {
                int2 cv = g_colval[i + lane];
                c = cv.x; v = __int_as_float(cv.y);
            }
            for (int j = 0; j < nb; j++) {
                int   cc = __shfl_sync(0xffffffffu, c, j);
                float vv = __shfl_sync(0xffffffffu, v, j);
                float4 xr = b1[(size_t)cc * ldb1 + lane];
                acc.x = fmaf(vv, xr.x, acc.x);
                acc.y = fmaf(vv, xr.y, acc.y);
                acc.z = fmaf(vv, xr.z, acc.z);
                acc.w = fmaf(vv, xr.w, acc.w);
            }
        }
        float4 s = S[(size_t)row * ldS + lane];
        float4 r;
        r.x = fmaf(two, acc.x, s.x);
        r.y = fmaf(two, acc.y, s.y);
        r.z = fmaf(two, acc.z, s.z);
        r.w = fmaf(two, acc.w, s.w);
        if (b2) {
            float4 tt = b2[(size_t)row * ldb2 + lane];
            r.x -= tt.x; r.y -= tt.y; r.z -= tt.z; r.w -= tt.w;
        }
        if (bias) {
            float4 bb = bias[lane];
            r.x += bb.x; r.y += bb.y; r.z += bb.z; r.w += bb.w;
        }
        dst[(size_t)row * 32 + lane] = r;
        if (stats) {
            int f = lane * 4;
            atomicAdd(&ssum[f],     r.x); atomicAdd(&ssq[f],     r.x * r.x);
            atomicAdd(&ssum[f + 1], r.y); atomicAdd(&ssq[f + 1], r.y * r.y);
            atomicAdd(&ssum[f + 2], r.z); atomicAdd(&ssq[f + 2], r.z * r.z);
            atomicAdd(&ssum[f + 3], r.w); atomicAdd(&ssq[f + 3], r.w * r.w);
        }
    }
    if (stats) {
        __syncthreads();
        if (threadIdx.x < 128) {
            atomicAdd(&g_bnsum[threadIdx.x], ssum[threadIdx.x]);
            atomicAdd(&g_bnsq [threadIdx.x], ssq [threadIdx.x]);
        }
    }
}

// ---------------- Clenshaw SpMM, 32 features ----------------
__global__ void cheb_spmm32(const float* __restrict__ b1, int ldb1,
                            const float* __restrict__ b2, int ldb2,
                            const float* __restrict__ S, int ldS,
                            float* __restrict__ dst,
                            const float* __restrict__ bias,
                            float two, int N, int stats) {
    __shared__ float ssum[32], ssq[32];
    int row = (blockIdx.x * blockDim.x + threadIdx.x) >> 5;
    int lane = threadIdx.x & 31;
    if (stats) {
        if (threadIdx.x < 32) { ssum[threadIdx.x] = 0.f; ssq[threadIdx.x] = 0.f; }
        __syncthreads();
    }
    if (row < N) {
        int start = g_rowptr[row], end = g_rowptr[row + 1];
        float acc = 0.f;
        for (int i = start; i < end; i += 32) {
            int nb = min(32, end - i);
            int c = 0; float v = 0.f;
            if (lane < nb) {
                int2 cv = g_colval[i + lane];
                c = cv.x; v = __int_as_float(cv.y);
            }
            for (int j = 0; j < nb; j++) {
                int   cc = __shfl_sync(0xffffffffu, c, j);
                float vv = __shfl_sync(0xffffffffu, v, j);
                acc = fmaf(vv, b1[(size_t)cc * ldb1 + lane], acc);
            }
        }
        float r = fmaf(two, acc, S[(size_t)row * ldS + lane]);
        if (b2)  r -= b2[(size_t)row * ldb2 + lane];
        if (bias) r += bias[lane];
        dst[(size_t)row * 32 + lane] = r;
        if (stats) {
            atomicAdd(&ssum[lane], r);
            atomicAdd(&ssq [lane], r * r);
        }
    }
    if (stats) {
        __syncthreads();
        if (threadIdx.x < 32) {
            atomicAdd(&g_bnsum[threadIdx.x], ssum[threadIdx.x]);
            atomicAdd(&g_bnsq [threadIdx.x], ssq [threadIdx.x]);
        }
    }
}

// ---------------- BatchNorm apply ----------------
__global__ void bn_apply_relu(const float* __restrict__ X, float* __restrict__ Y,
                              const float* __restrict__ gamma, const float* __restrict__ beta,
                              int N, int C) {
    int i = blockIdx.x * blockDim.x + threadIdx.x;
    if (i >= N * C) return;
    int c = i % C;
    float invN = 1.f / (float)N;
    float mu  = g_bnsum[c] * invN;
    float var = g_bnsq[c] * invN - mu * mu;
    float y = fmaf(gamma[c] * rsqrtf(var + 1e-5f), X[i] - mu, beta[c]);
    Y[i] = fmaxf(y, 0.f);
}

// ---------------- host ----------------
extern "C" void kernel_launch(void* const* d_in, const int* in_sizes, int n_in,
                              void* d_out, int out_size) {
    const float* x    = (const float*)d_in[0];
    const void*  ei   = d_in[1];
    const float* W1   = (const float*)d_in[2];
    const float* b1v  = (const float*)d_in[3];
    const float* W2   = (const float*)d_in[4];
    const float* b2v  = (const float*)d_in[5];
    const float* g1   = (const float*)d_in[6];
    const float* be1  = (const float*)d_in[7];
    const float* g2   = (const float*)d_in[8];
    const float* be2  = (const float*)d_in[9];
    float* out = (float*)d_out;

    int N = in_sizes[0] / FIN;
    int E = in_sizes[1] / 2;

    void* pv;
    cudaGetSymbolAddress(&pv, g_S1);  float* S1  = (float*)pv;
    cudaGetSymbolAddress(&pv, g_S2);  float* S2  = (float*)pv;
    cudaGetSymbolAddress(&pv, g_W1c); float* W1c = (float*)pv;
    cudaGetSymbolAddress(&pv, g_W2c); float* W2c = (float*)pv;
    cudaGetSymbolAddress(&pv, g_T0);  float* T0  = (float*)pv;
    cudaGetSymbolAddress(&pv, g_T1);  float* T1  = (float*)pv;
    cudaGetSymbolAddress(&pv, g_T2);  float* T2  = (float*)pv;
    cudaGetSymbolAddress(&pv, g_H);   float* H   = (float*)pv;

    static int smem_set = 0;
    if (!smem_set) {
        cudaFuncSetAttribute(gemm_tf32, cudaFuncAttributeMaxDynamicSharedMemorySize, GEMM_SMEM);
        smem_set = 1;
    }

    int gE = (E + 255) / 256;
    int gN = (N + 255) / 256;
    int gSp = (N * 32 + 255) / 256;
    int gM = (N + 127) / 128;

    // Launch order puts the big L1 GEMM at slot 4 (ncu capture target).
    init_zero<<<gN, 256>>>(N);                                       // 1
    detect_dtype<<<gE, 256>>>((const int*)ei, E);                    // 2
    concat_w1<<<(KCH * FIN * FH + 255) / 256, 256>>>(W1, W1c);       // 3
    gemm_tf32<<<dim3(gM, (KCH * FH) / 256), 256, GEMM_SMEM>>>(x, W1c, S1, N, KCH * FH); // 4
    degree_kernel<<<gE, 256>>>(ei, E);                               // 5
    dinv_kernel<<<gN, 256>>>(N);                                     // 6
    scan_kernel<<<1, 1024>>>(N);                                     // 7
    scatter_kernel<<<gE, 256>>>(ei, E);                              // 8
    concat_w2<<<(KCH * FH * FOUT + 255) / 256, 256>>>(W2, W2c);      // 9
    zero_bn<<<1, 128>>>(FH);                                         // 10

    float* bufs[3] = {T0, T1, T2};

    // ======== Layer 1 Clenshaw ========
    {
        const float4* b1p = (const float4*)(S1 + 15 * FH); int ldb1 = (KCH * FH) / 4;
        const float4* b2p = nullptr; int ldb2 = 0;
        int bi = 0;
        for (int k = 14; k >= 1; k--) {
            float4* d = (float4*)bufs[bi];
            cheb_spmm128<<<gSp, 256>>>(b1p, ldb1, b2p, ldb2,
                                       (const float4*)(S1 + k * FH), (KCH * FH) / 4,
                                       d, nullptr, 2.f, N, 0);
            b2p = b1p; ldb2 = ldb1;
            b1p = (const float4*)d; ldb1 = 32;
            bi = (bi + 1) % 3;
        }
        // final step: H = S_0 + L b_1 - b_2 + bias1, with fused BN stats
        cheb_spmm128<<<gSp, 256>>>(b1p, ldb1, b2p, ldb2,
                                   (const float4*)S1, (KCH * FH) / 4,
                                   (float4*)H, (const float4*)b1v, 1.f, N, 1);
    }
    bn_apply_relu<<<(N * FH + 255) / 256, 256>>>(H, H, g1, be1, N, FH);

    // ======== Layer 2 ========
    gemm_tf32<<<dim3(gM, (KCH * FOUT) / 256), 256, GEMM_SMEM>>>(H, W2c, S2, N, KCH * FOUT);
    zero_bn<<<1, 128>>>(FOUT);
    {
        const float* b1p = S2 + 15 * FOUT; int ldb1 = KCH * FOUT;
        const float* b2p = nullptr; int ldb2 = 0;
        int bi = 0;
        for (int k = 14; k >= 1; k--) {
            float* d = bufs[bi];
            cheb_spmm32<<<gSp, 256>>>(b1p, ldb1, b2p, ldb2,
                                      S2 + k * FOUT, KCH * FOUT,
                                      d, nullptr, 2.f, N, 0);
            b2p = b1p; ldb2 = ldb1;
            b1p = d; ldb1 = FOUT;
            bi = (bi + 1) % 3;
        }
        cheb_spmm32<<<gSp, 256>>>(b1p, ldb1, b2p, ldb2,
                                  S2, KCH * FOUT,
                                  out, b2v, 1.f, N, 1);
    }
    bn_apply_relu<<<(N * FOUT + 255) / 256, 256>>>(out, out, g2, be2, N, FOUT);
}

// round 4
// speedup vs baseline: 2.3628x; 1.0049x over previous
#include <cuda_runtime.h>
#include <cstdint>

#define NN   50000
#define EE   800000
#define FIN  128
#define FH   128
#define FOUT 32
#define KCH  16

// ---------------- device scratch ----------------
__device__ float g_S1[NN * (KCH * FH)];    // 50000 x 2048
__device__ float g_S2[NN * (KCH * FOUT)];  // 50000 x 512
__device__ float g_X [NN * FIN];           // tf32-rounded x
__device__ float g_W1c[FIN * KCH * FH];
__device__ float g_W2c[FH * KCH * FOUT];
__device__ float g_T0[NN * FH];
__device__ float g_T1[NN * FH];
__device__ float g_T2[NN * FH];
__device__ float g_H [NN * FH];
__device__ int   g_degi[NN];
__device__ int   g_cnt [NN];
__device__ int   g_rowptr[NN + 1];
__device__ int   g_cursor[NN];
__device__ float g_dinv[NN];
__device__ int2  g_colval[EE];
__device__ float g_bnsum[FH];
__device__ float g_bnsq [FH];
__device__ int   g_is32;

// ---------------- helpers ----------------
__device__ __forceinline__ float f2tf32f(float f) {
    unsigned r;
    asm("cvt.rna.tf32.f32 %0, %1;" : "=r"(r) : "f"(f));
    return __int_as_float(r);
}

__device__ __forceinline__ void mma_tf32(float* c, const unsigned* a, const unsigned* b) {
    asm volatile("mma.sync.aligned.m16n8k8.row.col.f32.tf32.tf32.f32 "
        "{%0,%1,%2,%3}, {%4,%5,%6,%7}, {%8,%9}, {%0,%1,%2,%3};"
        : "+f"(c[0]), "+f"(c[1]), "+f"(c[2]), "+f"(c[3])
        : "r"(a[0]), "r"(a[1]), "r"(a[2]), "r"(a[3]), "r"(b[0]), "r"(b[1]));
}

__device__ __forceinline__ void cp_async16(uint32_t dst, const void* src, int szbytes) {
    asm volatile("cp.async.cg.shared.global [%0], [%1], 16, %2;"
                 :: "r"(dst), "l"(src), "r"(szbytes));
}
__device__ __forceinline__ void cp_commit() {
    asm volatile("cp.async.commit_group;");
}
template <int NW>
__device__ __forceinline__ void cp_wait() {
    asm volatile("cp.async.wait_group %0;" :: "n"(NW));
}

// ---------------- build kernels ----------------
__global__ void init_zero(int N) {
    int i = blockIdx.x * blockDim.x + threadIdx.x;
    if (i < N) { g_degi[i] = 0; g_cnt[i] = 0; }
    if (i == 0) g_is32 = 0;
}

__global__ void zero_bn(int C) {
    int i = threadIdx.x;
    if (i < C) { g_bnsum[i] = 0.f; g_bnsq[i] = 0.f; }
}

__global__ void detect_dtype(const int* __restrict__ p, int E) {
    int i = blockIdx.x * blockDim.x + threadIdx.x;
    if (i < E) {
        if (p[2 * i + 1] != 0) g_is32 = 1;
    }
}

__global__ void cvt_x(const float4* __restrict__ x, float4* __restrict__ xc, int n4) {
    int i = blockIdx.x * blockDim.x + threadIdx.x;
    if (i >= n4) return;
    float4 v = x[i];
    v.x = f2tf32f(v.x); v.y = f2tf32f(v.y); v.z = f2tf32f(v.z); v.w = f2tf32f(v.w);
    xc[i] = v;
}

__device__ __forceinline__ void load_edge(const void* ei, int E, int e, int& s, int& d) {
    if (g_is32) {
        const int* p = (const int*)ei;
        s = p[e]; d = p[E + e];
    } else {
        const long long* p = (const long long*)ei;
        s = (int)p[e]; d = (int)p[E + e];
    }
}

__global__ void degree_kernel(const void* __restrict__ ei, int E) {
    int e = blockIdx.x * blockDim.x + threadIdx.x;
    if (e >= E) return;
    int s, d; load_edge(ei, E, e, s, d);
    if (s != d) { atomicAdd(&g_degi[s], 1); atomicAdd(&g_cnt[d], 1); }
}

__global__ void dinv_kernel(int N) {
    int i = blockIdx.x * blockDim.x + threadIdx.x;
    if (i >= N) return;
    int dg = g_degi[i];
    g_dinv[i] = (dg > 0) ? rsqrtf((float)dg) : 0.f;
}

__global__ void scan_kernel(int N) {
    __shared__ int warpsum[32];
    __shared__ int s_carry;
    __shared__ int s_chunk;
    int t = threadIdx.x, lane = t & 31, wid = t >> 5;
    if (t == 0) s_carry = 0;
    __syncthreads();
    for (int base = 0; base < N; base += 1024) {
        int idx = base + t;
        int v = (idx < N) ? g_cnt[idx] : 0;
        int x = v;
        #pragma unroll
        for (int off = 1; off < 32; off <<= 1) {
            int y = __shfl_up_sync(0xffffffffu, x, off);
            if (lane >= off) x += y;
        }
        if (lane == 31) warpsum[wid] = x;
        __syncthreads();
        if (wid == 0) {
            int w = warpsum[lane];
            int xw = w;
            #pragma unroll
            for (int off = 1; off < 32; off <<= 1) {
                int y = __shfl_up_sync(0xffffffffu, xw, off);
                if (lane >= off) xw += y;
            }
            warpsum[lane] = xw - w;
            if (lane == 31) s_chunk = xw;
        }
        __syncthreads();
        int excl = s_carry + warpsum[wid] + x - v;
        if (idx < N) { g_rowptr[idx] = excl; g_cursor[idx] = excl; }
        __syncthreads();
        if (t == 0) s_carry += s_chunk;
        __syncthreads();
    }
    if (threadIdx.x == 0) g_rowptr[N] = s_carry;
}

__global__ void scatter_kernel(const void* __restrict__ ei, int E) {
    int e = blockIdx.x * blockDim.x + threadIdx.x;
    if (e >= E) return;
    int s, d; load_edge(ei, E, e, s, d);
    if (s != d) {
        int pos = atomicAdd(&g_cursor[d], 1);
        float v = -g_dinv[s] * g_dinv[d];
        g_colval[pos] = make_int2(s, __float_as_int(v));
    }
}

// ---------------- weight concat (+ tf32 rounding) ----------------
__global__ void concat_w1(const float* __restrict__ W, float* __restrict__ Wc) {
    int idx = blockIdx.x * blockDim.x + threadIdx.x;
    if (idx >= KCH * FIN * FH) return;
    int k = idx >> 14;
    int f = (idx >> 7) & 127;
    int o = idx & 127;
    Wc[f * (KCH * FH) + k * FH + o] = f2tf32f(W[idx]);
}

__global__ void concat_w2(const float* __restrict__ W, float* __restrict__ Wc) {
    int idx = blockIdx.x * blockDim.x + threadIdx.x;
    if (idx >= KCH * FH * FOUT) return;
    int k = idx >> 12;
    int f = (idx >> 5) & 127;
    int o = idx & 31;
    Wc[f * (KCH * FOUT) + k * FOUT + o] = f2tf32f(W[idx]);
}

// ---------------- TF32 GEMM v3: C[N,NC] = A[N,128] @ B[128,NC] ----------------
// BM=128, BN=128, BK=32, 256 threads = 8 warps (2x4), warp tile 64x32.
// 2 CTAs/SM. Inputs pre-rounded to tf32 -> no cvt in inner loop.
#define SA_STRIDE 36
#define SB_STRIDE 132
#define SA_STAGE  (128 * SA_STRIDE)
#define SB_STAGE  (32 * SB_STRIDE)
#define GEMM_SMEM ((2 * SA_STAGE + 2 * SB_STAGE) * 4)

__global__ __launch_bounds__(256, 2) void gemm_tf32(const float* __restrict__ A,
                                                    const float* __restrict__ B,
                                                    float* __restrict__ C,
                                                    int N, int NC) {
    extern __shared__ float smem[];
    float* sA = smem;
    float* sB = smem + 2 * SA_STAGE;
    uint32_t sA_u = (uint32_t)__cvta_generic_to_shared(sA);
    uint32_t sB_u = (uint32_t)__cvta_generic_to_shared(sB);

    int t = threadIdx.x;
    int lane = t & 31;
    int warp = t >> 5;
    int wm0 = (warp & 1) * 64;
    int wn0 = (warp >> 1) * 32;
    int bm0 = blockIdx.x * 128;
    int bn0 = blockIdx.y * 128;

    float c[4][4][4];
    #pragma unroll
    for (int mi = 0; mi < 4; mi++)
        #pragma unroll
        for (int ni = 0; ni < 4; ni++)
            #pragma unroll
            for (int r = 0; r < 4; r++) c[mi][ni][r] = 0.f;

    auto prefetch = [&](int stage, int kt) {
        // A: 128x32 floats = 1024 16B-chunks (4 per thread)
        #pragma unroll
        for (int i = 0; i < 4; i++) {
            int id = t + i * 256;
            int row = id >> 3, c4 = id & 7;
            int gr = bm0 + row;
            int ok = (gr < N);
            int grs = ok ? gr : 0;
            uint32_t dst = sA_u + (stage * SA_STAGE + row * SA_STRIDE + c4 * 4) * 4;
            cp_async16(dst, &A[(size_t)grs * 128 + kt + c4 * 4], ok ? 16 : 0);
        }
        // B: 32x128 floats = 1024 16B-chunks
        #pragma unroll
        for (int i = 0; i < 4; i++) {
            int id = t + i * 256;
            int row = id >> 5, c4 = id & 31;
            uint32_t dst = sB_u + (stage * SB_STAGE + row * SB_STRIDE + c4 * 4) * 4;
            cp_async16(dst, &B[(size_t)(kt + row) * NC + bn0 + c4 * 4], 16);
        }
        cp_commit();
    };

    prefetch(0, 0);

    #pragma unroll
    for (int it = 0; it < 4; it++) {
        if (it < 3) prefetch((it + 1) & 1, (it + 1) * 32);
        if (it < 3) cp_wait<1>(); else cp_wait<0>();
        __syncthreads();

        const float* cA = sA + (it & 1) * SA_STAGE;
        const float* cB = sB + (it & 1) * SB_STAGE;
        #pragma unroll
        for (int k8 = 0; k8 < 32; k8 += 8) {
            unsigned a[4][4], b[4][2];
            #pragma unroll
            for (int mi = 0; mi < 4; mi++) {
                int row = wm0 + mi * 16 + (lane >> 2);
                int col = k8 + (lane & 3);
                a[mi][0] = __float_as_uint(cA[row * SA_STRIDE + col]);
                a[mi][1] = __float_as_uint(cA[(row + 8) * SA_STRIDE + col]);
                a[mi][2] = __float_as_uint(cA[row * SA_STRIDE + col + 4]);
                a[mi][3] = __float_as_uint(cA[(row + 8) * SA_STRIDE + col + 4]);
            }
            #pragma unroll
            for (int ni = 0; ni < 4; ni++) {
                int kk = k8 + (lane & 3);
                int nn = wn0 + ni * 8 + (lane >> 2);
                b[ni][0] = __float_as_uint(cB[kk * SB_STRIDE + nn]);
                b[ni][1] = __float_as_uint(cB[(kk + 4) * SB_STRIDE + nn]);
            }
            #pragma unroll
            for (int mi = 0; mi < 4; mi++)
                #pragma unroll
                for (int ni = 0; ni < 4; ni++)
                    mma_tf32(c[mi][ni], a[mi], b[ni]);
        }
        __syncthreads();
    }

    #pragma unroll
    for (int mi = 0; mi < 4; mi++) {
        #pragma unroll
        for (int ni = 0; ni < 4; ni++) {
            int gr = bm0 + wm0 + mi * 16 + (lane >> 2);
            int gc = bn0 + wn0 + ni * 8 + 2 * (lane & 3);
            if (gr < N)
                *(float2*)&C[(size_t)gr * NC + gc] = make_float2(c[mi][ni][0], c[mi][ni][1]);
            if (gr + 8 < N)
                *(float2*)&C[(size_t)(gr + 8) * NC + gc] = make_float2(c[mi][ni][2], c[mi][ni][3]);
        }
    }
}

// ---------------- Clenshaw SpMM, 128 features ----------------
__global__ void cheb_spmm128(const float4* __restrict__ b1, int ldb1,
                             const float4* __restrict__ b2, int ldb2,
                             const float4* __restrict__ S, int ldS,
                             float4* __restrict__ dst,
                             const float4* __restrict__ bias,
                             float two, int N, int stats) {
    __shared__ float ssum[128], ssq[128];
    int row = (blockIdx.x * blockDim.x + threadIdx.x) >> 5;
    int lane = threadIdx.x & 31;
    if (stats) {
        if (threadIdx.x < 128) { ssum[threadIdx.x] = 0.f; ssq[threadIdx.x] = 0.f; }
        __syncthreads();
    }
    if (row < N) {
        int start = g_rowptr[row], end = g_rowptr[row + 1];
        float4 acc = make_float4(0.f, 0.f, 0.f, 0.f);
        for (int i = start; i < end; i += 32) {
            int nb = min(32, end - i);
            int c = 0; float v = 0.f;
            if (lane < nb) {
                int2 cv = g_colval[i + lane];
                c = cv.x; v = __int_as_float(cv.y);
            }
            int j = 0;
            for (; j + 4 <= nb; j += 4) {
                int   c0 = __shfl_sync(0xffffffffu, c, j);
                int   c1 = __shfl_sync(0xffffffffu, c, j + 1);
                int   c2 = __shfl_sync(0xffffffffu, c, j + 2);
                int   c3 = __shfl_sync(0xffffffffu, c, j + 3);
                float v0 = __shfl_sync(0xffffffffu, v, j);
                float v1 = __shfl_sync(0xffffffffu, v, j + 1);
                float v2 = __shfl_sync(0xffffffffu, v, j + 2);
                float v3 = __shfl_sync(0xffffffffu, v, j + 3);
                float4 x0 = b1[(size_t)c0 * ldb1 + lane];
                float4 x1 = b1[(size_t)c1 * ldb1 + lane];
                float4 x2 = b1[(size_t)c2 * ldb1 + lane];
                float4 x3 = b1[(size_t)c3 * ldb1 + lane];
                acc.x = fmaf(v0, x0.x, acc.x); acc.y = fmaf(v0, x0.y, acc.y);
                acc.z = fmaf(v0, x0.z, acc.z); acc.w = fmaf(v0, x0.w, acc.w);
                acc.x = fmaf(v1, x1.x, acc.x); acc.y = fmaf(v1, x1.y, acc.y);
                acc.z = fmaf(v1, x1.z, acc.z); acc.w = fmaf(v1, x1.w, acc.w);
                acc.x = fmaf(v2, x2.x, acc.x); acc.y = fmaf(v2, x2.y, acc.y);
                acc.z = fmaf(v2, x2.z, acc.z); acc.w = fmaf(v2, x2.w, acc.w);
                acc.x = fmaf(v3, x3.x, acc.x); acc.y = fmaf(v3, x3.y, acc.y);
                acc.z = fmaf(v3, x3.z, acc.z); acc.w = fmaf(v3, x3.w, acc.w);
            }
            for (; j < nb; j++) {
                int   cc = __shfl_sync(0xffffffffu, c, j);
                float vv = __shfl_sync(0xffffffffu, v, j);
                float4 xr = b1[(size_t)cc * ldb1 + lane];
                acc.x = fmaf(vv, xr.x, acc.x);
                acc.y = fmaf(vv, xr.y, acc.y);
                acc.z = fmaf(vv, xr.z, acc.z);
                acc.w = fmaf(vv, xr.w, acc.w);
            }
        }
        float4 s = S[(size_t)row * ldS + lane];
        float4 r;
        r.x = fmaf(two, acc.x, s.x);
        r.y = fmaf(two, acc.y, s.y);
        r.z = fmaf(two, acc.z, s.z);
        r.w = fmaf(two, acc.w, s.w);
        if (b2) {
            float4 tt = b2[(size_t)row * ldb2 + lane];
            r.x -= tt.x; r.y -= tt.y; r.z -= tt.z; r.w -= tt.w;
        }
        if (bias) {
            float4 bb = bias[lane];
            r.x += bb.x; r.y += bb.y; r.z += bb.z; r.w += bb.w;
        }
        dst[(size_t)row * 32 + lane] = r;
        if (stats) {
            int f = lane * 4;
            atomicAdd(&ssum[f],     r.x); atomicAdd(&ssq[f],     r.x * r.x);
            atomicAdd(&ssum[f + 1], r.y); atomicAdd(&ssq[f + 1], r.y * r.y);
            atomicAdd(&ssum[f + 2], r.z); atomicAdd(&ssq[f + 2], r.z * r.z);
            atomicAdd(&ssum[f + 3], r.w); atomicAdd(&ssq[f + 3], r.w * r.w);
        }
    }
    if (stats) {
        __syncthreads();
        if (threadIdx.x < 128) {
            atomicAdd(&g_bnsum[threadIdx.x], ssum[threadIdx.x]);
            atomicAdd(&g_bnsq [threadIdx.x], ssq [threadIdx.x]);
        }
    }
}

// ---------------- Clenshaw SpMM, 32 features ----------------
__global__ void cheb_spmm32(const float* __restrict__ b1, int ldb1,
                            const float* __restrict__ b2, int ldb2,
                            const float* __restrict__ S, int ldS,
                            float* __restrict__ dst,
                            const float* __restrict__ bias,
                            float two, int N, int stats) {
    __shared__ float ssum[32], ssq[32];
    int row = (blockIdx.x * blockDim.x + threadIdx.x) >> 5;
    int lane = threadIdx.x & 31;
    if (stats) {
        if (threadIdx.x < 32) { ssum[threadIdx.x] = 0.f; ssq[threadIdx.x] = 0.f; }
        __syncthreads();
    }
    if (row < N) {
        int start = g_rowptr[row], end = g_rowptr[row + 1];
        float acc = 0.f;
        for (int i = start; i < end; i += 32) {
            int nb = min(32, end - i);
            int c = 0; float v = 0.f;
            if (lane < nb) {
                int2 cv = g_colval[i + lane];
                c = cv.x; v = __int_as_float(cv.y);
            }
            int j = 0;
            for (; j + 4 <= nb; j += 4) {
                int   c0 = __shfl_sync(0xffffffffu, c, j);
                int   c1 = __shfl_sync(0xffffffffu, c, j + 1);
                int   c2 = __shfl_sync(0xffffffffu, c, j + 2);
                int   c3 = __shfl_sync(0xffffffffu, c, j + 3);
                float v0 = __shfl_sync(0xffffffffu, v, j);
                float v1 = __shfl_sync(0xffffffffu, v, j + 1);
                float v2 = __shfl_sync(0xffffffffu, v, j + 2);
                float v3 = __shfl_sync(0xffffffffu, v, j + 3);
                float x0 = b1[(size_t)c0 * ldb1 + lane];
                float x1 = b1[(size_t)c1 * ldb1 + lane];
                float x2 = b1[(size_t)c2 * ldb1 + lane];
                float x3 = b1[(size_t)c3 * ldb1 + lane];
                acc = fmaf(v0, x0, acc);
                acc = fmaf(v1, x1, acc);
                acc = fmaf(v2, x2, acc);
                acc = fmaf(v3, x3, acc);
            }
            for (; j < nb; j++) {
                int   cc = __shfl_sync(0xffffffffu, c, j);
                float vv = __shfl_sync(0xffffffffu, v, j);
                acc = fmaf(vv, b1[(size_t)cc * ldb1 + lane], acc);
            }
        }
        float r = fmaf(two, acc, S[(size_t)row * ldS + lane]);
        if (b2)  r -= b2[(size_t)row * ldb2 + lane];
        if (bias) r += bias[lane];
        dst[(size_t)row * 32 + lane] = r;
        if (stats) {
            atomicAdd(&ssum[lane], r);
            atomicAdd(&ssq [lane], r * r);
        }
    }
    if (stats) {
        __syncthreads();
        if (threadIdx.x < 32) {
            atomicAdd(&g_bnsum[threadIdx.x], ssum[threadIdx.x]);
            atomicAdd(&g_bnsq [threadIdx.x], ssq [threadIdx.x]);
        }
    }
}

// ---------------- BatchNorm apply ----------------
__global__ void bn_apply_relu(const float* __restrict__ X, float* __restrict__ Y,
                              const float* __restrict__ gamma, const float* __restrict__ beta,
                              int N, int C, int toTf32) {
    int i = blockIdx.x * blockDim.x + threadIdx.x;
    if (i >= N * C) return;
    int c = i % C;
    float invN = 1.f / (float)N;
    float mu  = g_bnsum[c] * invN;
    float var = g_bnsq[c] * invN - mu * mu;
    float y = fmaf(gamma[c] * rsqrtf(var + 1e-5f), X[i] - mu, beta[c]);
    y = fmaxf(y, 0.f);
    Y[i] = toTf32 ? f2tf32f(y) : y;
}

// ---------------- host ----------------
extern "C" void kernel_launch(void* const* d_in, const int* in_sizes, int n_in,
                              void* d_out, int out_size) {
    const float* x    = (const float*)d_in[0];
    const void*  ei   = d_in[1];
    const float* W1   = (const float*)d_in[2];
    const float* b1v  = (const float*)d_in[3];
    const float* W2   = (const float*)d_in[4];
    const float* b2v  = (const float*)d_in[5];
    const float* g1   = (const float*)d_in[6];
    const float* be1  = (const float*)d_in[7];
    const float* g2   = (const float*)d_in[8];
    const float* be2  = (const float*)d_in[9];
    float* out = (float*)d_out;

    int N = in_sizes[0] / FIN;
    int E = in_sizes[1] / 2;

    void* pv;
    cudaGetSymbolAddress(&pv, g_S1);  float* S1  = (float*)pv;
    cudaGetSymbolAddress(&pv, g_S2);  float* S2  = (float*)pv;
    cudaGetSymbolAddress(&pv, g_X);   float* Xc  = (float*)pv;
    cudaGetSymbolAddress(&pv, g_W1c); float* W1c = (float*)pv;
    cudaGetSymbolAddress(&pv, g_W2c); float* W2c = (float*)pv;
    cudaGetSymbolAddress(&pv, g_T0);  float* T0  = (float*)pv;
    cudaGetSymbolAddress(&pv, g_T1);  float* T1  = (float*)pv;
    cudaGetSymbolAddress(&pv, g_T2);  float* T2  = (float*)pv;
    cudaGetSymbolAddress(&pv, g_H);   float* H   = (float*)pv;

    static int smem_set = 0;
    if (!smem_set) {
        cudaFuncSetAttribute(gemm_tf32, cudaFuncAttributeMaxDynamicSharedMemorySize, GEMM_SMEM);
        smem_set = 1;
    }

    int gE = (E + 255) / 256;
    int gN = (N + 255) / 256;
    int gSp = (N * 32 + 255) / 256;
    int gM = (N + 127) / 128;

    // slot 4 = big L1 GEMM (ncu capture target)
    init_zero<<<gN, 256>>>(N);                                            // 1
    cvt_x<<<(N * FIN / 4 + 255) / 256, 256>>>((const float4*)x, (float4*)Xc, N * FIN / 4); // 2
    concat_w1<<<(KCH * FIN * FH + 255) / 256, 256>>>(W1, W1c);            // 3
    gemm_tf32<<<dim3(gM, (KCH * FH) / 128), 256, GEMM_SMEM>>>(Xc, W1c, S1, N, KCH * FH); // 4
    detect_dtype<<<gE, 256>>>((const int*)ei, E);                         // 5
    degree_kernel<<<gE, 256>>>(ei, E);                                    // 6
    dinv_kernel<<<gN, 256>>>(N);                                          // 7
    scan_kernel<<<1, 1024>>>(N);                                          // 8
    scatter_kernel<<<gE, 256>>>(ei, E);                                   // 9
    concat_w2<<<(KCH * FH * FOUT + 255) / 256, 256>>>(W2, W2c);           // 10
    zero_bn<<<1, 128>>>(FH);                                              // 11

    float* bufs[3] = {T0, T1, T2};

    // ======== Layer 1 Clenshaw ========
    {
        const float4* b1p = (const float4*)(S1 + 15 * FH); int ldb1 = (KCH * FH) / 4;
        const float4* b2p = nullptr; int ldb2 = 0;
        int bi = 0;
        for (int k = 14; k >= 1; k--) {
            float4* d = (float4*)bufs[bi];
            cheb_spmm128<<<gSp, 256>>>(b1p, ldb1, b2p, ldb2,
                                       (const float4*)(S1 + k * FH), (KCH * FH) / 4,
                                       d, nullptr, 2.f, N, 0);
            b2p = b1p; ldb2 = ldb1;
            b1p = (const float4*)d; ldb1 = 32;
            bi = (bi + 1) % 3;
        }
        cheb_spmm128<<<gSp, 256>>>(b1p, ldb1, b2p, ldb2,
                                   (const float4*)S1, (KCH * FH) / 4,
                                   (float4*)H, (const float4*)b1v, 1.f, N, 1);
    }
    bn_apply_relu<<<(N * FH + 255) / 256, 256>>>(H, H, g1, be1, N, FH, 1);

    // ======== Layer 2 ========
    gemm_tf32<<<dim3(gM, (KCH * FOUT) / 128), 256, GEMM_SMEM>>>(H, W2c, S2, N, KCH * FOUT);
    zero_bn<<<1, 128>>>(FOUT);
    {
        const float* b1p = S2 + 15 * FOUT; int ldb1 = KCH * FOUT;
        const float* b2p = nullptr; int ldb2 = 0;
        int bi = 0;
        for (int k = 14; k >= 1; k--) {
            float* d = bufs[bi];
            cheb_spmm32<<<gSp, 256>>>(b1p, ldb1, b2p, ldb2,
                                      S2 + k * FOUT, KCH * FOUT,
                                      d, nullptr, 2.f, N, 0);
            b2p = b1p; ldb2 = ldb1;
            b1p = d; ldb1 = FOUT;
            bi = (bi + 1) % 3;
        }
        cheb_spmm32<<<gSp, 256>>>(b1p, ldb1, b2p, ldb2,
                                  S2, KCH * FOUT,
                                  out, b2v, 1.f, N, 1);
    }
    bn_apply_relu<<<(N * FOUT + 255) / 256, 256>>>(out, out, g2, be2, N, FOUT, 0);
}

// round 5
// speedup vs baseline: 2.4295x; 1.0282x over previous
#include <cuda_runtime.h>
#include <cuda_fp16.h>
#include <cstdint>

#define NN   50000
#define EE   800000
#define FIN  128
#define FH   128
#define FOUT 32
#define KCH  16

// ---------------- device scratch ----------------
__device__ float g_S1[NN * (KCH * FH)];    // 50000 x 2048
__device__ float g_S2[NN * (KCH * FOUT)];  // 50000 x 512
__device__ float g_X [NN * FIN];           // tf32-rounded x
__device__ float g_W1c[FIN * KCH * FH];
__device__ float g_W2c[FH * KCH * FOUT];
__device__ float g_T0[NN * FH];
__device__ float g_T1[NN * FH];
__device__ float g_T2[NN * FH];
__device__ __half g_h0[NN * FH];
__device__ __half g_h1[NN * FH];
__device__ __half g_h2[NN * FH];
__device__ float g_H [NN * FH];
__device__ int   g_degi[NN];
__device__ int   g_cnt [NN];
__device__ int   g_rowptr[NN + 1];
__device__ int   g_cursor[NN];
__device__ float g_dinv[NN];
__device__ int2  g_colval[EE];
__device__ float g_bnsum1[FH];
__device__ float g_bnsq1 [FH];
__device__ float g_bnsum2[FOUT];
__device__ float g_bnsq2 [FOUT];
__device__ int   g_is32;

// ---------------- helpers ----------------
__device__ __forceinline__ float f2tf32f(float f) {
    unsigned r;
    asm("cvt.rna.tf32.f32 %0, %1;" : "=r"(r) : "f"(f));
    return __int_as_float(r);
}

__device__ __forceinline__ void mma_tf32(float* c, const unsigned* a, const unsigned* b) {
    asm volatile("mma.sync.aligned.m16n8k8.row.col.f32.tf32.tf32.f32 "
        "{%0,%1,%2,%3}, {%4,%5,%6,%7}, {%8,%9}, {%0,%1,%2,%3};"
        : "+f"(c[0]), "+f"(c[1]), "+f"(c[2]), "+f"(c[3])
        : "r"(a[0]), "r"(a[1]), "r"(a[2]), "r"(a[3]), "r"(b[0]), "r"(b[1]));
}

__device__ __forceinline__ void cp_async16(uint32_t dst, const void* src, int szbytes) {
    asm volatile("cp.async.cg.shared.global [%0], [%1], 16, %2;"
                 :: "r"(dst), "l"(src), "r"(szbytes));
}
__device__ __forceinline__ void cp_commit() {
    asm volatile("cp.async.commit_group;");
}
template <int NW>
__device__ __forceinline__ void cp_wait() {
    asm volatile("cp.async.wait_group %0;" :: "n"(NW));
}

// ---------------- build kernels ----------------
__global__ void init_zero(int N) {
    int i = blockIdx.x * blockDim.x + threadIdx.x;
    if (i < N) { g_degi[i] = 0; g_cnt[i] = 0; }
    if (i < FH)   { g_bnsum1[i] = 0.f; g_bnsq1[i] = 0.f; }
    if (i < FOUT) { g_bnsum2[i] = 0.f; g_bnsq2[i] = 0.f; }
    if (i == 0) g_is32 = 0;
}

__global__ void detect_dtype(const int* __restrict__ p, int E) {
    int i = blockIdx.x * blockDim.x + threadIdx.x;
    if (i < E) {
        if (p[2 * i + 1] != 0) g_is32 = 1;
    }
}

__global__ void cvt_x(const float4* __restrict__ x, float4* __restrict__ xc, int n4) {
    int i = blockIdx.x * blockDim.x + threadIdx.x;
    if (i >= n4) return;
    float4 v = x[i];
    v.x = f2tf32f(v.x); v.y = f2tf32f(v.y); v.z = f2tf32f(v.z); v.w = f2tf32f(v.w);
    xc[i] = v;
}

__device__ __forceinline__ void load_edge(const void* ei, int E, int e, int& s, int& d) {
    if (g_is32) {
        const int* p = (const int*)ei;
        s = p[e]; d = p[E + e];
    } else {
        const long long* p = (const long long*)ei;
        s = (int)p[e]; d = (int)p[E + e];
    }
}

__global__ void degree_kernel(const void* __restrict__ ei, int E) {
    int e = blockIdx.x * blockDim.x + threadIdx.x;
    if (e >= E) return;
    int s, d; load_edge(ei, E, e, s, d);
    if (s != d) { atomicAdd(&g_degi[s], 1); atomicAdd(&g_cnt[d], 1); }
}

__global__ void dinv_kernel(int N) {
    int i = blockIdx.x * blockDim.x + threadIdx.x;
    if (i >= N) return;
    int dg = g_degi[i];
    g_dinv[i] = (dg > 0) ? rsqrtf((float)dg) : 0.f;
}

__global__ void scan_kernel(int N) {
    __shared__ int warpsum[32];
    __shared__ int s_carry;
    __shared__ int s_chunk;
    int t = threadIdx.x, lane = t & 31, wid = t >> 5;
    if (t == 0) s_carry = 0;
    __syncthreads();
    for (int base = 0; base < N; base += 1024) {
        int idx = base + t;
        int v = (idx < N) ? g_cnt[idx] : 0;
        int x = v;
        #pragma unroll
        for (int off = 1; off < 32; off <<= 1) {
            int y = __shfl_up_sync(0xffffffffu, x, off);
            if (lane >= off) x += y;
        }
        if (lane == 31) warpsum[wid] = x;
        __syncthreads();
        if (wid == 0) {
            int w = warpsum[lane];
            int xw = w;
            #pragma unroll
            for (int off = 1; off < 32; off <<= 1) {
                int y = __shfl_up_sync(0xffffffffu, xw, off);
                if (lane >= off) xw += y;
            }
            warpsum[lane] = xw - w;
            if (lane == 31) s_chunk = xw;
        }
        __syncthreads();
        int excl = s_carry + warpsum[wid] + x - v;
        if (idx < N) { g_rowptr[idx] = excl; g_cursor[idx] = excl; }
        __syncthreads();
        if (t == 0) s_carry += s_chunk;
        __syncthreads();
    }
    if (threadIdx.x == 0) g_rowptr[N] = s_carry;
}

__global__ void scatter_kernel(const void* __restrict__ ei, int E) {
    int e = blockIdx.x * blockDim.x + threadIdx.x;
    if (e >= E) return;
    int s, d; load_edge(ei, E, e, s, d);
    if (s != d) {
        int pos = atomicAdd(&g_cursor[d], 1);
        float v = -g_dinv[s] * g_dinv[d];
        g_colval[pos] = make_int2(s, __float_as_int(v));
    }
}

// ---------------- weight concat (+ tf32 rounding) ----------------
__global__ void concat_w1(const float* __restrict__ W, float* __restrict__ Wc) {
    int idx = blockIdx.x * blockDim.x + threadIdx.x;
    if (idx >= KCH * FIN * FH) return;
    int k = idx >> 14;
    int f = (idx >> 7) & 127;
    int o = idx & 127;
    Wc[f * (KCH * FH) + k * FH + o] = f2tf32f(W[idx]);
}

__global__ void concat_w2(const float* __restrict__ W, float* __restrict__ Wc) {
    int idx = blockIdx.x * blockDim.x + threadIdx.x;
    if (idx >= KCH * FH * FOUT) return;
    int k = idx >> 12;
    int f = (idx >> 5) & 127;
    int o = idx & 31;
    Wc[f * (KCH * FOUT) + k * FOUT + o] = f2tf32f(W[idx]);
}

// ---------------- TF32 GEMM: C[N,NC] = A[N,128] @ B[128,NC] ----------------
#define SA_STRIDE 36
#define SB_STRIDE 132
#define SA_STAGE  (128 * SA_STRIDE)
#define SB_STAGE  (32 * SB_STRIDE)
#define GEMM_SMEM ((2 * SA_STAGE + 2 * SB_STAGE) * 4)

__global__ __launch_bounds__(256, 2) void gemm_tf32(const float* __restrict__ A,
                                                    const float* __restrict__ B,
                                                    float* __restrict__ C,
                                                    int N, int NC) {
    extern __shared__ float smem[];
    float* sA = smem;
    float* sB = smem + 2 * SA_STAGE;
    uint32_t sA_u = (uint32_t)__cvta_generic_to_shared(sA);
    uint32_t sB_u = (uint32_t)__cvta_generic_to_shared(sB);

    int t = threadIdx.x;
    int lane = t & 31;
    int warp = t >> 5;
    int wm0 = (warp & 1) * 64;
    int wn0 = (warp >> 1) * 32;
    int bm0 = blockIdx.x * 128;
    int bn0 = blockIdx.y * 128;

    float c[4][4][4];
    #pragma unroll
    for (int mi = 0; mi < 4; mi++)
        #pragma unroll
        for (int ni = 0; ni < 4; ni++)
            #pragma unroll
            for (int r = 0; r < 4; r++) c[mi][ni][r] = 0.f;

    auto prefetch = [&](int stage, int kt) {
        #pragma unroll
        for (int i = 0; i < 4; i++) {
            int id = t + i * 256;
            int row = id >> 3, c4 = id & 7;
            int gr = bm0 + row;
            int ok = (gr < N);
            int grs = ok ? gr : 0;
            uint32_t dst = sA_u + (stage * SA_STAGE + row * SA_STRIDE + c4 * 4) * 4;
            cp_async16(dst, &A[(size_t)grs * 128 + kt + c4 * 4], ok ? 16 : 0);
        }
        #pragma unroll
        for (int i = 0; i < 4; i++) {
            int id = t + i * 256;
            int row = id >> 5, c4 = id & 31;
            uint32_t dst = sB_u + (stage * SB_STAGE + row * SB_STRIDE + c4 * 4) * 4;
            cp_async16(dst, &B[(size_t)(kt + row) * NC + bn0 + c4 * 4], 16);
        }
        cp_commit();
    };

    prefetch(0, 0);

    #pragma unroll
    for (int it = 0; it < 4; it++) {
        if (it < 3) prefetch((it + 1) & 1, (it + 1) * 32);
        if (it < 3) cp_wait<1>(); else cp_wait<0>();
        __syncthreads();

        const float* cA = sA + (it & 1) * SA_STAGE;
        const float* cB = sB + (it & 1) * SB_STAGE;
        #pragma unroll
        for (int k8 = 0; k8 < 32; k8 += 8) {
            unsigned a[4][4], b[4][2];
            #pragma unroll
            for (int mi = 0; mi < 4; mi++) {
                int row = wm0 + mi * 16 + (lane >> 2);
                int col = k8 + (lane & 3);
                a[mi][0] = __float_as_uint(cA[row * SA_STRIDE + col]);
                a[mi][1] = __float_as_uint(cA[(row + 8) * SA_STRIDE + col]);
                a[mi][2] = __float_as_uint(cA[row * SA_STRIDE + col + 4]);
                a[mi][3] = __float_as_uint(cA[(row + 8) * SA_STRIDE + col + 4]);
            }
            #pragma unroll
            for (int ni = 0; ni < 4; ni++) {
                int kk = k8 + (lane & 3);
                int nn = wn0 + ni * 8 + (lane >> 2);
                b[ni][0] = __float_as_uint(cB[kk * SB_STRIDE + nn]);
                b[ni][1] = __float_as_uint(cB[(kk + 4) * SB_STRIDE + nn]);
            }
            #pragma unroll
            for (int mi = 0; mi < 4; mi++)
                #pragma unroll
                for (int ni = 0; ni < 4; ni++)
                    mma_tf32(c[mi][ni], a[mi], b[ni]);
        }
        __syncthreads();
    }

    #pragma unroll
    for (int mi = 0; mi < 4; mi++) {
        #pragma unroll
        for (int ni = 0; ni < 4; ni++) {
            int gr = bm0 + wm0 + mi * 16 + (lane >> 2);
            int gc = bn0 + wn0 + ni * 8 + 2 * (lane & 3);
            if (gr < N)
                *(float2*)&C[(size_t)gr * NC + gc] = make_float2(c[mi][ni][0], c[mi][ni][1]);
            if (gr + 8 < N)
                *(float2*)&C[(size_t)(gr + 8) * NC + gc] = make_float2(c[mi][ni][2], c[mi][ni][3]);
        }
    }
}

// ---------------- Clenshaw SpMM, 128 features ----------------
// dst = S + two*(L@b1) - b2 (+bias). Gather operand is fp16 (b1h) when USEH,
// else fp32 (b1f). Dual-writes fp32 dst and (optionally) fp16 dsth.
template <int USEH>
__global__ void cheb_spmm128(const uint2* __restrict__ b1h,
                             const float4* __restrict__ b1f, int ldb1f,
                             const float4* __restrict__ b2, int ldb2,
                             const float4* __restrict__ S, int ldS,
                             float4* __restrict__ dst,
                             uint2* __restrict__ dsth,
                             const float4* __restrict__ bias,
                             float two, int N, int stats) {
    __shared__ float ssum[128], ssq[128];
    int row = (blockIdx.x * blockDim.x + threadIdx.x) >> 5;
    int lane = threadIdx.x & 31;
    if (stats) {
        if (threadIdx.x < 128) { ssum[threadIdx.x] = 0.f; ssq[threadIdx.x] = 0.f; }
        __syncthreads();
    }
    if (row < N) {
        int start = g_rowptr[row], end = g_rowptr[row + 1];
        float4 acc = make_float4(0.f, 0.f, 0.f, 0.f);
        for (int i = start; i < end; i += 32) {
            int nb = min(32, end - i);
            int c = 0; float v = 0.f;
            if (lane < nb) {
                int2 cv = g_colval[i + lane];
                c = cv.x; v = __int_as_float(cv.y);
            }
            #pragma unroll 4
            for (int j = 0; j < nb; j++) {
                int   cc = __shfl_sync(0xffffffffu, c, j);
                float vv = __shfl_sync(0xffffffffu, v, j);
                if (USEH) {
                    uint2 u = b1h[(size_t)cc * 32 + lane];
                    float2 f01 = __half22float2(*(const __half2*)&u.x);
                    float2 f23 = __half22float2(*(const __half2*)&u.y);
                    acc.x = fmaf(vv, f01.x, acc.x);
                    acc.y = fmaf(vv, f01.y, acc.y);
                    acc.z = fmaf(vv, f23.x, acc.z);
                    acc.w = fmaf(vv, f23.y, acc.w);
                } else {
                    float4 xr = b1f[(size_t)cc * ldb1f + lane];
                    acc.x = fmaf(vv, xr.x, acc.x);
                    acc.y = fmaf(vv, xr.y, acc.y);
                    acc.z = fmaf(vv, xr.z, acc.z);
                    acc.w = fmaf(vv, xr.w, acc.w);
                }
            }
        }
        float4 s = S[(size_t)row * ldS + lane];
        float4 r;
        r.x = fmaf(two, acc.x, s.x);
        r.y = fmaf(two, acc.y, s.y);
        r.z = fmaf(two, acc.z, s.z);
        r.w = fmaf(two, acc.w, s.w);
        if (b2) {
            float4 tt = b2[(size_t)row * ldb2 + lane];
            r.x -= tt.x; r.y -= tt.y; r.z -= tt.z; r.w -= tt.w;
        }
        if (bias) {
            float4 bb = bias[lane];
            r.x += bb.x; r.y += bb.y; r.z += bb.z; r.w += bb.w;
        }
        dst[(size_t)row * 32 + lane] = r;
        if (dsth) {
            __half2 h01 = __floats2half2_rn(r.x, r.y);
            __half2 h23 = __floats2half2_rn(r.z, r.w);
            uint2 u;
            u.x = *(unsigned*)&h01;
            u.y = *(unsigned*)&h23;
            dsth[(size_t)row * 32 + lane] = u;
        }
        if (stats) {
            int f = lane * 4;
            atomicAdd(&ssum[f],     r.x); atomicAdd(&ssq[f],     r.x * r.x);
            atomicAdd(&ssum[f + 1], r.y); atomicAdd(&ssq[f + 1], r.y * r.y);
            atomicAdd(&ssum[f + 2], r.z); atomicAdd(&ssq[f + 2], r.z * r.z);
            atomicAdd(&ssum[f + 3], r.w); atomicAdd(&ssq[f + 3], r.w * r.w);
        }
    }
    if (stats) {
        __syncthreads();
        if (threadIdx.x < 128) {
            atomicAdd(&g_bnsum1[threadIdx.x], ssum[threadIdx.x]);
            atomicAdd(&g_bnsq1 [threadIdx.x], ssq [threadIdx.x]);
        }
    }
}

// ---------------- Clenshaw SpMM, 32 features ----------------
template <int USEH>
__global__ void cheb_spmm32(const __half* __restrict__ b1h,
                            const float* __restrict__ b1f, int ldb1f,
                            const float* __restrict__ b2, int ldb2,
                            const float* __restrict__ S, int ldS,
                            float* __restrict__ dst,
                            __half* __restrict__ dsth,
                            const float* __restrict__ bias,
                            float two, int N, int stats) {
    __shared__ float ssum[32], ssq[32];
    int row = (blockIdx.x * blockDim.x + threadIdx.x) >> 5;
    int lane = threadIdx.x & 31;
    if (stats) {
        if (threadIdx.x < 32) { ssum[threadIdx.x] = 0.f; ssq[threadIdx.x] = 0.f; }
        __syncthreads();
    }
    if (row < N) {
        int start = g_rowptr[row], end = g_rowptr[row + 1];
        float acc = 0.f;
        for (int i = start; i < end; i += 32) {
            int nb = min(32, end - i);
            int c = 0; float v = 0.f;
            if (lane < nb) {
                int2 cv = g_colval[i + lane];
                c = cv.x; v = __int_as_float(cv.y);
            }
            #pragma unroll 4
            for (int j = 0; j < nb; j++) {
                int   cc = __shfl_sync(0xffffffffu, c, j);
                float vv = __shfl_sync(0xffffffffu, v, j);
                float xv;
                if (USEH) xv = __half2float(b1h[(size_t)cc * 32 + lane]);
                else      xv = b1f[(size_t)cc * ldb1f + lane];
                acc = fmaf(vv, xv, acc);
            }
        }
        float r = fmaf(two, acc, S[(size_t)row * ldS + lane]);
        if (b2)  r -= b2[(size_t)row * ldb2 + lane];
        if (bias) r += bias[lane];
        dst[(size_t)row * 32 + lane] = r;
        if (dsth) dsth[(size_t)row * 32 + lane] = __float2half_rn(r);
        if (stats) {
            atomicAdd(&ssum[lane], r);
            atomicAdd(&ssq [lane], r * r);
        }
    }
    if (stats) {
        __syncthreads();
        if (threadIdx.x < 32) {
            atomicAdd(&g_bnsum2[threadIdx.x], ssum[threadIdx.x]);
            atomicAdd(&g_bnsq2 [threadIdx.x], ssq [threadIdx.x]);
        }
    }
}

// ---------------- BatchNorm apply ----------------
__global__ void bn_apply_relu(const float* __restrict__ X, float* __restrict__ Y,
                              const float* __restrict__ gamma, const float* __restrict__ beta,
                              const float* __restrict__ bnsum, const float* __restrict__ bnsq,
                              int N, int C, int toTf32) {
    int i = blockIdx.x * blockDim.x + threadIdx.x;
    if (i >= N * C) return;
    int c = i % C;
    float invN = 1.f / (float)N;
    float mu  = bnsum[c] * invN;
    float var = bnsq[c] * invN - mu * mu;
    float y = fmaf(gamma[c] * rsqrtf(var + 1e-5f), X[i] - mu, beta[c]);
    y = fmaxf(y, 0.f);
    Y[i] = toTf32 ? f2tf32f(y) : y;
}

// ---------------- host ----------------
extern "C" void kernel_launch(void* const* d_in, const int* in_sizes, int n_in,
                              void* d_out, int out_size) {
    const float* x    = (const float*)d_in[0];
    const void*  ei   = d_in[1];
    const float* W1   = (const float*)d_in[2];
    const float* b1v  = (const float*)d_in[3];
    const float* W2   = (const float*)d_in[4];
    const float* b2v  = (const float*)d_in[5];
    const float* g1   = (const float*)d_in[6];
    const float* be1  = (const float*)d_in[7];
    const float* g2   = (const float*)d_in[8];
    const float* be2  = (const float*)d_in[9];
    float* out = (float*)d_out;

    int N = in_sizes[0] / FIN;
    int E = in_sizes[1] / 2;

    void* pv;
    cudaGetSymbolAddress(&pv, g_S1);  float* S1  = (float*)pv;
    cudaGetSymbolAddress(&pv, g_S2);  float* S2  = (float*)pv;
    cudaGetSymbolAddress(&pv, g_X);   float* Xc  = (float*)pv;
    cudaGetSymbolAddress(&pv, g_W1c); float* W1c = (float*)pv;
    cudaGetSymbolAddress(&pv, g_W2c); float* W2c = (float*)pv;
    cudaGetSymbolAddress(&pv, g_T0);  float* T0  = (float*)pv;
    cudaGetSymbolAddress(&pv, g_T1);  float* T1  = (float*)pv;
    cudaGetSymbolAddress(&pv, g_T2);  float* T2  = (float*)pv;
    cudaGetSymbolAddress(&pv, g_h0);  __half* H0 = (__half*)pv;
    cudaGetSymbolAddress(&pv, g_h1);  __half* H1 = (__half*)pv;
    cudaGetSymbolAddress(&pv, g_h2);  __half* H2 = (__half*)pv;
    cudaGetSymbolAddress(&pv, g_H);   float* H   = (float*)pv;
    cudaGetSymbolAddress(&pv, g_bnsum1); float* bns1 = (float*)pv;
    cudaGetSymbolAddress(&pv, g_bnsq1);  float* bnq1 = (float*)pv;
    cudaGetSymbolAddress(&pv, g_bnsum2); float* bns2 = (float*)pv;
    cudaGetSymbolAddress(&pv, g_bnsq2);  float* bnq2 = (float*)pv;

    static int smem_set = 0;
    if (!smem_set) {
        cudaFuncSetAttribute(gemm_tf32, cudaFuncAttributeMaxDynamicSharedMemorySize, GEMM_SMEM);
        smem_set = 1;
    }

    int gE = (E + 255) / 256;
    int gN = (N + 255) / 256;
    int gSp = (N * 32 + 255) / 256;
    int gM = (N + 127) / 128;

    // slot 4 = big L1 GEMM (ncu capture target)
    init_zero<<<gN, 256>>>(N);                                            // 1
    cvt_x<<<(N * FIN / 4 + 255) / 256, 256>>>((const float4*)x, (float4*)Xc, N * FIN / 4); // 2
    concat_w1<<<(KCH * FIN * FH + 255) / 256, 256>>>(W1, W1c);            // 3
    gemm_tf32<<<dim3(gM, (KCH * FH) / 128), 256, GEMM_SMEM>>>(Xc, W1c, S1, N, KCH * FH); // 4
    detect_dtype<<<gE, 256>>>((const int*)ei, E);                         // 5
    degree_kernel<<<gE, 256>>>(ei, E);                                    // 6
    dinv_kernel<<<gN, 256>>>(N);                                          // 7
    scan_kernel<<<1, 1024>>>(N);                                          // 8
    scatter_kernel<<<gE, 256>>>(ei, E);                                   // 9
    concat_w2<<<(KCH * FH * FOUT + 255) / 256, 256>>>(W2, W2c);           // 10

    float*  fb[3] = {T0, T1, T2};
    __half* hb[3] = {H0, H1, H2};

    // ======== Layer 1 Clenshaw ========
    {
        // current b1: fp32 = S1 col-block 15 (fp16 twin: none yet)
        const uint2*  b1h = nullptr;
        const float4* b1f = (const float4*)(S1 + 15 * FH); int ldb1f = (KCH * FH) / 4;
        const float4* b2p = nullptr; int ldb2 = 0;
        int bi = 0;
        for (int k = 14; k >= 1; k--) {
            float4* df = (float4*)fb[bi];
            uint2*  dh = (uint2*)hb[bi];
            if (b1h)
                cheb_spmm128<1><<<gSp, 256>>>(b1h, nullptr, 0, b2p, ldb2,
                                              (const float4*)(S1 + k * FH), (KCH * FH) / 4,
                                              df, dh, nullptr, 2.f, N, 0);
            else
                cheb_spmm128<0><<<gSp, 256>>>(nullptr, b1f, ldb1f, b2p, ldb2,
                                              (const float4*)(S1 + k * FH), (KCH * FH) / 4,
                                              df, dh, nullptr, 2.f, N, 0);
            b2p = b1f; ldb2 = ldb1f;          // fp32 twin of old b1 becomes b2
            b1f = df; ldb1f = 32;
            b1h = dh;
            bi = (bi + 1) % 3;
        }
        // final: H = S_0 + L b_1 - b_2 + bias1, fused BN stats
        cheb_spmm128<1><<<gSp, 256>>>(b1h, nullptr, 0, b2p, ldb2,
                                      (const float4*)S1, (KCH * FH) / 4,
                                      (float4*)H, nullptr, (const float4*)b1v, 1.f, N, 1);
    }
    bn_apply_relu<<<(N * FH + 255) / 256, 256>>>(H, H, g1, be1, bns1, bnq1, N, FH, 1);

    // ======== Layer 2 ========
    gemm_tf32<<<dim3(gM, (KCH * FOUT) / 128), 256, GEMM_SMEM>>>(H, W2c, S2, N, KCH * FOUT);
    {
        const __half* b1h = nullptr;
        const float*  b1f = S2 + 15 * FOUT; int ldb1f = KCH * FOUT;
        const float*  b2p = nullptr; int ldb2 = 0;
        int bi = 0;
        for (int k = 14; k >= 1; k--) {
            float*  df = fb[bi];
            __half* dh = hb[bi];
            if (b1h)
                cheb_spmm32<1><<<gSp, 256>>>(b1h, nullptr, 0, b2p, ldb2,
                                             S2 + k * FOUT, KCH * FOUT,
                                             df, dh, nullptr, 2.f, N, 0);
            else
                cheb_spmm32<0><<<gSp, 256>>>(nullptr, b1f, ldb1f, b2p, ldb2,
                                             S2 + k * FOUT, KCH * FOUT,
                                             df, dh, nullptr, 2.f, N, 0);
            b2p = b1f; ldb2 = ldb1f;
            b1f = df; ldb1f = FOUT;
            b1h = dh;
            bi = (bi + 1) % 3;
        }
        cheb_spmm32<1><<<gSp, 256>>>(b1h, nullptr, 0, b2p, ldb2,
                                     S2, KCH * FOUT,
                                     out, nullptr, b2v, 1.f, N, 1);
    }
    bn_apply_relu<<<(N * FOUT + 255) / 256, 256>>>(out, out, g2, be2, bns2, bnq2, N, FOUT, 0);
}